// round 1
// baseline (speedup 1.0000x reference)
#include <cuda_runtime.h>
#include <math.h>

#define NB 16
#define NDOC 2
#define NQ 16
#define DSEQ 512
#define HDIM 256
#define NHEAD 8
#define HSZ 32
#define NLAYER 2
#define KRBF 128
#define DPOOL 255
#define NSEQ (NB*NDOC)          // 32
#define NROWS (NSEQ*DSEQ)       // 16384
#define NQROWS (NB*NQ)          // 256
#define NBQ (NSEQ*NQ)           // 512
#define NRBFROWS (NBQ*DPOOL)    // 130560

// ------------------------- scratch (static device, no allocs) -------------------
__device__ float g_X[NROWS*HDIM];
__device__ float g_T[NROWS*HDIM];
__device__ float g_FF[NROWS*HDIM];
__device__ float g_QKV[NROWS*3*HDIM];
__device__ float g_S[(size_t)NSEQ*NHEAD*DSEQ*DSEQ];   // 268 MB attention scores
__device__ float g_O[NROWS*HDIM];
__device__ float g_QE[NQROWS*HDIM];
__device__ float g_QT[NQROWS*HDIM];
__device__ float g_QN[NQROWS*HDIM];
__device__ float g_DN[NROWS*HDIM];
__device__ float g_COS[NBQ*DSEQ];
__device__ float g_YR[(size_t)NRBFROWS*KRBF];
__device__ float g_HR[(size_t)NRBFROWS*HDIM];
__device__ float g_SV[NRBFROWS];
__device__ float g_SC[NBQ];

// ------------------------- embedding + positional encoding ---------------------
__global__ void embed_doc_kernel(const int* __restrict__ dtok, const float* __restrict__ embw,
                                 float* __restrict__ X) {
  int idx = blockIdx.x*256 + threadIdx.x;
  int h = idx & (HDIM-1);
  int row = idx >> 8;              // bn*512 + t
  int t = row & (DSEQ-1);
  int tok = dtok[row];
  int i = h >> 1;
  float div = expf((float)i * -0.07195578415606394f);   // exp(2i * -ln(10000)/256)
  float ang = (float)t * div;
  float pe = (h & 1) ? cosf(ang) : sinf(ang);
  X[idx] = embw[(size_t)tok*HDIM + h] + pe;
}

__global__ void embed_q_kernel(const int* __restrict__ qtok, const float* __restrict__ embw,
                               float* __restrict__ QE) {
  int idx = blockIdx.x*256 + threadIdx.x;
  int h = idx & (HDIM-1), row = idx >> 8;
  QE[idx] = embw[(size_t)qtok[row]*HDIM + h];
}

// ------------------------- generic tiled fp32 GEMM: C = A@B + bias -------------
// M,N multiples of 64; K multiple of 16.
template<bool RELU>
__global__ void gemm_bias_kernel(const float* __restrict__ A, const float* __restrict__ Bm,
                                 const float* __restrict__ bias, float* __restrict__ C,
                                 int M, int N, int Kd) {
  __shared__ float As[16][65];
  __shared__ float Bs[16][64];
  const int tx = threadIdx.x, ty = threadIdx.y;
  const int tid = ty*16 + tx;
  const int row0 = blockIdx.y*64, col0 = blockIdx.x*64;
  float acc[4][4] = {};
  for (int kt = 0; kt < Kd; kt += 16) {
    int r = tid >> 2;
    int k4 = (tid & 3) << 2;
    float4 av = *(const float4*)(A + (size_t)(row0 + r)*Kd + kt + k4);
    As[k4+0][r] = av.x; As[k4+1][r] = av.y; As[k4+2][r] = av.z; As[k4+3][r] = av.w;
    int kb = tid >> 4;
    int c4 = (tid & 15) << 2;
    *(float4*)&Bs[kb][c4] = *(const float4*)(Bm + (size_t)(kt + kb)*N + col0 + c4);
    __syncthreads();
    #pragma unroll
    for (int k = 0; k < 16; k++) {
      float a[4], bv[4];
      #pragma unroll
      for (int i = 0; i < 4; i++) a[i] = As[k][ty*4+i];
      #pragma unroll
      for (int j = 0; j < 4; j++) bv[j] = Bs[k][tx*4+j];
      #pragma unroll
      for (int i = 0; i < 4; i++)
        #pragma unroll
        for (int j = 0; j < 4; j++)
          acc[i][j] = fmaf(a[i], bv[j], acc[i][j]);
    }
    __syncthreads();
  }
  #pragma unroll
  for (int i = 0; i < 4; i++) {
    int rr = row0 + ty*4 + i;
    #pragma unroll
    for (int j = 0; j < 4; j++) {
      int cc = col0 + tx*4 + j;
      float v = acc[i][j] + bias[cc];
      if (RELU) v = fmaxf(v, 0.f);
      C[(size_t)rr*N + cc] = v;
    }
  }
}

// ------------------------- attention ------------------------------------------
__global__ void attn_scores_kernel(const float* __restrict__ QKV, float* __restrict__ S) {
  const int bnh = blockIdx.z, bn = bnh >> 3, h = bnh & 7;
  const float* Qp = QKV + (size_t)bn*DSEQ*768 + h*HSZ;
  const float* Kp = Qp + HDIM;
  __shared__ float Qs[32][65];
  __shared__ float Ks[32][65];
  const int tx = threadIdx.x, ty = threadIdx.y;
  const int tid = ty*16+tx;
  const int q0 = blockIdx.y*64, k0 = blockIdx.x*64;
  #pragma unroll
  for (int i = 0; i < 8; i++) {
    int idx = tid + i*256;
    int m = idx >> 5, kk = idx & 31;
    Qs[kk][m] = Qp[(size_t)(q0+m)*768 + kk];
    Ks[kk][m] = Kp[(size_t)(k0+m)*768 + kk];
  }
  __syncthreads();
  float acc[4][4] = {};
  #pragma unroll 8
  for (int k = 0; k < 32; k++) {
    float a[4], bv[4];
    #pragma unroll
    for (int i = 0; i < 4; i++) a[i] = Qs[k][ty*4+i];
    #pragma unroll
    for (int j = 0; j < 4; j++) bv[j] = Ks[k][tx*4+j];
    #pragma unroll
    for (int i = 0; i < 4; i++)
      #pragma unroll
      for (int j = 0; j < 4; j++)
        acc[i][j] = fmaf(a[i], bv[j], acc[i][j]);
  }
  float* Sp = S + (size_t)bnh*DSEQ*DSEQ;
  const float scale = 0.17677669529663687f;  // 1/sqrt(32)
  #pragma unroll
  for (int i = 0; i < 4; i++)
    #pragma unroll
    for (int j = 0; j < 4; j++)
      Sp[(size_t)(q0+ty*4+i)*DSEQ + k0+tx*4+j] = acc[i][j]*scale;
}

__global__ void softmax_kernel(float* __restrict__ S, const float* __restrict__ mask_d) {
  int row = blockIdx.x*8 + (threadIdx.x >> 5);     // bnh*512 + q
  int lane = threadIdx.x & 31;
  int bn = row >> 12;
  float* Sp = S + (size_t)row*DSEQ;
  const float* mp = mask_d + bn*DSEQ;
  float v[16]; float mx = -1e30f;
  #pragma unroll
  for (int i = 0; i < 16; i++) {
    int k = lane + i*32;
    float x = (mp[k] > 0.f) ? Sp[k] : -1e9f;
    v[i] = x; mx = fmaxf(mx, x);
  }
  #pragma unroll
  for (int off = 16; off; off >>= 1) mx = fmaxf(mx, __shfl_xor_sync(0xffffffffu, mx, off));
  float sum = 0.f;
  #pragma unroll
  for (int i = 0; i < 16; i++) { v[i] = __expf(v[i] - mx); sum += v[i]; }
  #pragma unroll
  for (int off = 16; off; off >>= 1) sum += __shfl_xor_sync(0xffffffffu, sum, off);
  float inv = 1.f / sum;
  #pragma unroll
  for (int i = 0; i < 16; i++) Sp[lane + i*32] = v[i]*inv;
}

__global__ void attn_pv_kernel(const float* __restrict__ S, const float* __restrict__ QKV,
                               float* __restrict__ O) {
  const int bnh = blockIdx.y, bn = bnh >> 3, h = bnh & 7;
  const int q0 = blockIdx.x*64;
  const float* Sp = S + (size_t)bnh*DSEQ*DSEQ;
  const float* Vp = QKV + (size_t)bn*DSEQ*768 + 2*HDIM + h*HSZ;
  __shared__ float Ps[32][65];
  __shared__ float Vs[32][33];
  const int tx = threadIdx.x, ty = threadIdx.y;
  const int tid = ty*16+tx;
  float acc[4][2] = {};
  for (int kt = 0; kt < DSEQ; kt += 32) {
    #pragma unroll
    for (int i = 0; i < 8; i++) {
      int idx = tid + i*256; int m = idx >> 5, k = idx & 31;
      Ps[k][m] = Sp[(size_t)(q0+m)*DSEQ + kt + k];
    }
    #pragma unroll
    for (int i = 0; i < 4; i++) {
      int idx = tid + i*256; int k = idx >> 5, n = idx & 31;
      Vs[k][n] = Vp[(size_t)(kt+k)*768 + n];
    }
    __syncthreads();
    #pragma unroll 8
    for (int k = 0; k < 32; k++) {
      float b0 = Vs[k][tx*2], b1 = Vs[k][tx*2+1];
      #pragma unroll
      for (int i = 0; i < 4; i++) {
        float a = Ps[k][ty*4+i];
        acc[i][0] = fmaf(a, b0, acc[i][0]);
        acc[i][1] = fmaf(a, b1, acc[i][1]);
      }
    }
    __syncthreads();
  }
  #pragma unroll
  for (int i = 0; i < 4; i++)
    #pragma unroll
    for (int j = 0; j < 2; j++)
      O[(size_t)(bn*DSEQ + q0 + ty*4 + i)*HDIM + h*HSZ + tx*2 + j] = acc[i][j];
}

// ------------------------- residual + LayerNorm --------------------------------
__global__ void add_ln_kernel(const float* __restrict__ Xin, const float* __restrict__ Y,
                              const float* __restrict__ g, const float* __restrict__ b,
                              float* __restrict__ Out) {
  __shared__ float red[256];
  int row = blockIdx.x, tid = threadIdx.x;
  float v = Xin[(size_t)row*HDIM + tid] + Y[(size_t)row*HDIM + tid];
  red[tid] = v; __syncthreads();
  for (int s = 128; s > 0; s >>= 1) { if (tid < s) red[tid] += red[tid+s]; __syncthreads(); }
  float mean = red[0] * (1.f/HDIM);
  __syncthreads();
  float dv = v - mean;
  red[tid] = dv*dv; __syncthreads();
  for (int s = 128; s > 0; s >>= 1) { if (tid < s) red[tid] += red[tid+s]; __syncthreads(); }
  float var = red[0] * (1.f/HDIM);
  Out[(size_t)row*HDIM + tid] = dv * rsqrtf(var + 1e-5f) * g[tid] + b[tid];
}

// ------------------------- cosine head ------------------------------------------
__global__ void rownorm_kernel(const float* __restrict__ In, float* __restrict__ Out) {
  __shared__ float red[256];
  int row = blockIdx.x, tid = threadIdx.x;
  float v = In[(size_t)row*HDIM + tid];
  red[tid] = v*v; __syncthreads();
  for (int s=128; s>0; s>>=1){ if(tid<s) red[tid]+=red[tid+s]; __syncthreads(); }
  float n = fmaxf(sqrtf(red[0]), 1e-8f);
  Out[(size_t)row*HDIM + tid] = v / n;
}

__global__ void dc_norm_kernel(const int* __restrict__ dtok, const float* __restrict__ embw,
                               const float* __restrict__ Xf, const float* __restrict__ wc,
                               const float* __restrict__ bc, float* __restrict__ DN) {
  __shared__ float red[256];
  int row = blockIdx.x, tid = threadIdx.x;
  float de = embw[(size_t)dtok[row]*HDIM + tid];
  float v = wc[0]*de + wc[1]*Xf[(size_t)row*HDIM + tid] + bc[0];
  red[tid] = v*v; __syncthreads();
  for (int s=128;s>0;s>>=1){ if(tid<s) red[tid]+=red[tid+s]; __syncthreads(); }
  float n = fmaxf(sqrtf(red[0]), 1e-8f);
  DN[(size_t)row*HDIM + tid] = v / n;
}

__global__ void cos_kernel(const float* __restrict__ QN, const float* __restrict__ DN,
                           float* __restrict__ COS) {
  __shared__ float Qs[NQ*HDIM];
  int bn = blockIdx.y;
  int b = bn >> 1;
  int t = blockIdx.x*128 + threadIdx.x;
  for (int i = threadIdx.x; i < NQ*HDIM; i += 128) Qs[i] = QN[(size_t)b*NQ*HDIM + i];
  __syncthreads();
  const float* dp = DN + ((size_t)bn*DSEQ + t)*HDIM;
  float acc[NQ] = {};
  for (int hh = 0; hh < HDIM; hh++) {
    float dv = dp[hh];
    #pragma unroll
    for (int qq = 0; qq < NQ; qq++) acc[qq] = fmaf(dv, Qs[qq*HDIM+hh], acc[qq]);
  }
  #pragma unroll
  for (int qq = 0; qq < NQ; qq++)
    COS[((size_t)bn*NQ + qq)*DSEQ + t] = acc[qq];
}

// ------------------------- RBF pooling + MLP ------------------------------------
// y[row, k] with row = (bn*16+q)*255 + dp : y = log(1e-6 + sum_{j<4} mask*exp(-50(c-mu)^2))
__global__ void rbf_y_kernel(const float* __restrict__ COS, const float* __restrict__ mask_d,
                             float* __restrict__ Y) {
  size_t idx = (size_t)blockIdx.x*256 + threadIdx.x;
  int k = (int)(idx & (KRBF-1));
  int row = (int)(idx >> 7);
  int dp = row % DPOOL;
  int bq = row / DPOOL;
  int bn = bq >> 4;
  const float* cr = COS + (size_t)bq*DSEQ + dp*2;
  const float* mr = mask_d + bn*DSEQ + dp*2;
  float mu = 1.f - (float)k*(2.f/KRBF);
  float s = 0.f;
  #pragma unroll
  for (int j = 0; j < 4; j++) {
    float c = cr[j] - mu;
    s += mr[j]*__expf(-50.f*c*c);
  }
  Y[idx] = __logf(s + 1e-6f);
}

__global__ void rbf_s_kernel(const float* __restrict__ Hm, const float* __restrict__ w2,
                             const float* __restrict__ b2, float* __restrict__ SV) {
  int row = blockIdx.x*8 + (threadIdx.x>>5);
  int lane = threadIdx.x & 31;
  const float* hp = Hm + (size_t)row*HDIM;
  float acc = 0.f;
  #pragma unroll
  for (int i = 0; i < 8; i++) acc = fmaf(hp[lane + i*32], w2[lane + i*32], acc);
  for (int off=16; off; off>>=1) acc += __shfl_xor_sync(0xffffffffu, acc, off);
  if (lane==0) SV[row] = acc + b2[0];
}

__global__ void final_max_kernel(const float* __restrict__ SV, float* __restrict__ SC) {
  __shared__ float red[256];
  int bq = blockIdx.x, tid = threadIdx.x;
  float mx = (tid < DPOOL) ? SV[(size_t)bq*DPOOL + tid] : -1e30f;
  red[tid] = mx; __syncthreads();
  for (int s=128;s>0;s>>=1){ if(tid<s) red[tid]=fmaxf(red[tid],red[tid+s]); __syncthreads(); }
  if (tid==0) SC[bq] = red[0];
}

__global__ void final_sum_kernel(const float* __restrict__ SC, const float* __restrict__ mask_q,
                                 float* __restrict__ out) {
  int bn = threadIdx.x;       // 32
  int b = bn >> 1;
  float s = 0.f;
  #pragma unroll
  for (int qq = 0; qq < NQ; qq++)
    s += SC[bn*NQ + qq] * mask_q[b*NQ + qq];
  out[bn] = s;
}

// ------------------------- launcher ---------------------------------------------
extern "C" void kernel_launch(void* const* d_in, const int* in_sizes, int n_in,
                              void* d_out, int out_size) {
  const int*   qtok     = (const int*)d_in[0];
  const int*   dtok     = (const int*)d_in[1];
  const float* mask_q   = (const float*)d_in[2];
  const float* mask_d   = (const float*)d_in[3];
  const float* embw     = (const float*)d_in[4];
  const float* fc_qt_w  = (const float*)d_in[5];
  const float* fc_qt_b  = (const float*)d_in[6];
  const float* qkv_w    = (const float*)d_in[7];
  const float* qkv_b    = (const float*)d_in[8];
  const float* out_w    = (const float*)d_in[9];
  const float* out_b    = (const float*)d_in[10];
  const float* ln1_g    = (const float*)d_in[11];
  const float* ln1_b    = (const float*)d_in[12];
  const float* w1       = (const float*)d_in[13];
  const float* b1       = (const float*)d_in[14];
  const float* w2       = (const float*)d_in[15];
  const float* b2       = (const float*)d_in[16];
  const float* ln2_g    = (const float*)d_in[17];
  const float* ln2_b    = (const float*)d_in[18];
  const float* fc_ctx_w = (const float*)d_in[19];
  const float* fc_ctx_b = (const float*)d_in[20];
  const float* rb1w     = (const float*)d_in[21];
  const float* rb1b     = (const float*)d_in[22];
  const float* rb2w     = (const float*)d_in[23];
  const float* rb2b     = (const float*)d_in[24];
  float* out = (float*)d_out;

  void* p;
  cudaGetSymbolAddress(&p, g_X);   float* X   = (float*)p;
  cudaGetSymbolAddress(&p, g_T);   float* T   = (float*)p;
  cudaGetSymbolAddress(&p, g_FF);  float* FF  = (float*)p;
  cudaGetSymbolAddress(&p, g_QKV); float* QKV = (float*)p;
  cudaGetSymbolAddress(&p, g_S);   float* S   = (float*)p;
  cudaGetSymbolAddress(&p, g_O);   float* O   = (float*)p;
  cudaGetSymbolAddress(&p, g_QE);  float* QE  = (float*)p;
  cudaGetSymbolAddress(&p, g_QT);  float* QT  = (float*)p;
  cudaGetSymbolAddress(&p, g_QN);  float* QN  = (float*)p;
  cudaGetSymbolAddress(&p, g_DN);  float* DN  = (float*)p;
  cudaGetSymbolAddress(&p, g_COS); float* COS = (float*)p;
  cudaGetSymbolAddress(&p, g_YR);  float* YR  = (float*)p;
  cudaGetSymbolAddress(&p, g_HR);  float* HR  = (float*)p;
  cudaGetSymbolAddress(&p, g_SV);  float* SV  = (float*)p;
  cudaGetSymbolAddress(&p, g_SC);  float* SC  = (float*)p;

  dim3 blk(16,16);

  embed_doc_kernel<<<NROWS*HDIM/256, 256>>>(dtok, embw, X);

  for (int l = 0; l < NLAYER; l++) {
    gemm_bias_kernel<false><<<dim3(768/64, NROWS/64), blk>>>(
        X, qkv_w + (size_t)l*HDIM*768, qkv_b + l*768, QKV, NROWS, 768, HDIM);
    attn_scores_kernel<<<dim3(8,8,NSEQ*NHEAD), blk>>>(QKV, S);
    softmax_kernel<<<NSEQ*NHEAD*DSEQ/8, 256>>>(S, mask_d);
    attn_pv_kernel<<<dim3(8,NSEQ*NHEAD), blk>>>(S, QKV, O);
    gemm_bias_kernel<false><<<dim3(4, NROWS/64), blk>>>(
        O, out_w + (size_t)l*HDIM*HDIM, out_b + l*HDIM, T, NROWS, HDIM, HDIM);
    add_ln_kernel<<<NROWS,256>>>(X, T, ln1_g+l*HDIM, ln1_b+l*HDIM, X);
    gemm_bias_kernel<true><<<dim3(4, NROWS/64), blk>>>(
        X, w1 + (size_t)l*HDIM*HDIM, b1 + l*HDIM, FF, NROWS, HDIM, HDIM);
    gemm_bias_kernel<false><<<dim3(4, NROWS/64), blk>>>(
        FF, w2 + (size_t)l*HDIM*HDIM, b2 + l*HDIM, T, NROWS, HDIM, HDIM);
    add_ln_kernel<<<NROWS,256>>>(X, T, ln2_g+l*HDIM, ln2_b+l*HDIM, X);
  }

  embed_q_kernel<<<NQROWS*HDIM/256,256>>>(qtok, embw, QE);
  gemm_bias_kernel<false><<<dim3(4, NQROWS/64), blk>>>(QE, fc_qt_w, fc_qt_b, QT, NQROWS, HDIM, HDIM);
  rownorm_kernel<<<NQROWS,256>>>(QT, QN);
  dc_norm_kernel<<<NROWS,256>>>(dtok, embw, X, fc_ctx_w, fc_ctx_b, DN);
  cos_kernel<<<dim3(DSEQ/128, NSEQ),128>>>(QN, DN, COS);

  rbf_y_kernel<<<NRBFROWS*KRBF/256, 256>>>(COS, mask_d, YR);
  gemm_bias_kernel<true><<<dim3(4, NRBFROWS/64), blk>>>(YR, rb1w, rb1b, HR, NRBFROWS, HDIM, KRBF);
  rbf_s_kernel<<<NRBFROWS/8, 256>>>(HR, rb2w, rb2b, SV);
  final_max_kernel<<<NBQ,256>>>(SV, SC);
  final_sum_kernel<<<1,32>>>(SC, mask_q, out);
}

// round 2
// speedup vs baseline: 1.4566x; 1.4566x over previous
#include <cuda_runtime.h>
#include <math.h>
#include <stdint.h>

#define NB 16
#define NDOC 2
#define NQ 16
#define DSEQ 512
#define HDIM 256
#define NHEAD 8
#define HSZ 32
#define NLAYER 2
#define KRBF 128
#define DPOOL 255
#define NSEQ (NB*NDOC)          // 32
#define NROWS (NSEQ*DSEQ)       // 16384
#define NQROWS (NB*NQ)          // 256
#define NBQ (NSEQ*NQ)           // 512
#define NRBFROWS (NBQ*DPOOL)    // 130560

// ------------------------- scratch (static device, no allocs) -------------------
__device__ float g_X[NROWS*HDIM];
__device__ float g_T[NROWS*HDIM];
__device__ float g_FF[NROWS*HDIM];
__device__ float g_QKV[NROWS*3*HDIM];
__device__ float g_S[(size_t)NSEQ*NHEAD*DSEQ*DSEQ];   // 268 MB attention scores
__device__ float g_O[NROWS*HDIM];
__device__ float g_QE[NQROWS*HDIM];
__device__ float g_QT[NQROWS*HDIM];
__device__ float g_QN[NQROWS*HDIM];
__device__ float g_DN[NROWS*HDIM];
__device__ float g_COS[NBQ*DSEQ];
__device__ float g_YR[(size_t)NRBFROWS*KRBF];
__device__ float g_HR[(size_t)NRBFROWS*HDIM];
__device__ float g_SV[NRBFROWS];
__device__ float g_SC[NBQ];

// ------------------------- embedding + positional encoding ---------------------
__global__ void embed_doc_kernel(const int* __restrict__ dtok, const float* __restrict__ embw,
                                 float* __restrict__ X) {
  int idx = blockIdx.x*256 + threadIdx.x;
  int h = idx & (HDIM-1);
  int row = idx >> 8;              // bn*512 + t
  int t = row & (DSEQ-1);
  int tok = dtok[row];
  int i = h >> 1;
  float div = expf((float)i * -0.07195578415606394f);   // exp(2i * -ln(10000)/256)
  float ang = (float)t * div;
  float pe = (h & 1) ? cosf(ang) : sinf(ang);
  X[idx] = embw[(size_t)tok*HDIM + h] + pe;
}

__global__ void embed_q_kernel(const int* __restrict__ qtok, const float* __restrict__ embw,
                               float* __restrict__ QE) {
  int idx = blockIdx.x*256 + threadIdx.x;
  int h = idx & (HDIM-1), row = idx >> 8;
  QE[idx] = embw[(size_t)qtok[row]*HDIM + h];
}

// ------------------------- tf32 tensor-core GEMM: C = A@B + bias ----------------
// A: M x K row-major fp32;  B: K x N row-major fp32.
// M multiple of 128, N multiple of 128, K multiple of 16.
__device__ __forceinline__ float to_tf32(float x) {
  uint32_t u;
  asm("cvt.rna.tf32.f32 %0, %1;" : "=r"(u) : "f"(x));
  return __uint_as_float(u);
}

__device__ __forceinline__ void mma_tf32(float* c, const float* a, const float* b) {
  asm volatile(
    "mma.sync.aligned.m16n8k8.row.col.f32.tf32.tf32.f32 "
    "{%0,%1,%2,%3}, {%4,%5,%6,%7}, {%8,%9}, {%0,%1,%2,%3};"
    : "+f"(c[0]), "+f"(c[1]), "+f"(c[2]), "+f"(c[3])
    : "r"(__float_as_uint(a[0])), "r"(__float_as_uint(a[1])),
      "r"(__float_as_uint(a[2])), "r"(__float_as_uint(a[3])),
      "r"(__float_as_uint(b[0])), "r"(__float_as_uint(b[1])));
}

#define AS_STRIDE 20
#define BS_STRIDE 136

template<bool RELU>
__global__ void __launch_bounds__(256)
gemm_tf32_kernel(const float* __restrict__ A, const float* __restrict__ Bm,
                 const float* __restrict__ bias, float* __restrict__ C,
                 int M, int N, int Kd) {
  __shared__ float As[128][AS_STRIDE];
  __shared__ float Bs[16][BS_STRIDE];

  const int tid = threadIdx.x;
  const int warp = tid >> 5, lane = tid & 31;
  const int gid = lane >> 2, tig = lane & 3;
  const int warpM = warp >> 2, warpN = warp & 3;   // 2 x 4 warp grid
  const int mBase = warpM*64, nBase = warpN*32;
  const int rowB = blockIdx.y*128, colB = blockIdx.x*128;

  float acc[4][4][4];
  #pragma unroll
  for (int i = 0; i < 4; i++)
    #pragma unroll
    for (int j = 0; j < 4; j++)
      #pragma unroll
      for (int k = 0; k < 4; k++) acc[i][j][k] = 0.f;

  for (int kt = 0; kt < Kd; kt += 16) {
    // load A tile 128x16
    #pragma unroll
    for (int it = 0; it < 2; it++) {
      int slot = tid + it*256;
      int r = slot >> 2, c4 = (slot & 3) << 2;
      float4 v = *(const float4*)(A + (size_t)(rowB + r)*Kd + kt + c4);
      v.x = to_tf32(v.x); v.y = to_tf32(v.y); v.z = to_tf32(v.z); v.w = to_tf32(v.w);
      *(float4*)&As[r][c4] = v;
    }
    // load B tile 16x128
    #pragma unroll
    for (int it = 0; it < 2; it++) {
      int slot = tid + it*256;
      int kr = slot >> 5, c4 = (slot & 31) << 2;
      float4 v = *(const float4*)(Bm + (size_t)(kt + kr)*N + colB + c4);
      v.x = to_tf32(v.x); v.y = to_tf32(v.y); v.z = to_tf32(v.z); v.w = to_tf32(v.w);
      *(float4*)&Bs[kr][c4] = v;
    }
    __syncthreads();

    #pragma unroll
    for (int ks = 0; ks < 2; ks++) {
      float afr[4][4], bfr[4][2];
      #pragma unroll
      for (int mt = 0; mt < 4; mt++) {
        int r0 = mBase + mt*16 + gid;
        afr[mt][0] = As[r0    ][ks*8 + tig    ];
        afr[mt][1] = As[r0 + 8][ks*8 + tig    ];
        afr[mt][2] = As[r0    ][ks*8 + tig + 4];
        afr[mt][3] = As[r0 + 8][ks*8 + tig + 4];
      }
      #pragma unroll
      for (int nt = 0; nt < 4; nt++) {
        int n0 = nBase + nt*8 + gid;
        bfr[nt][0] = Bs[ks*8 + tig    ][n0];
        bfr[nt][1] = Bs[ks*8 + tig + 4][n0];
      }
      #pragma unroll
      for (int mt = 0; mt < 4; mt++)
        #pragma unroll
        for (int nt = 0; nt < 4; nt++)
          mma_tf32(acc[mt][nt], afr[mt], bfr[nt]);
    }
    __syncthreads();
  }

  // epilogue: bias (+relu) and store
  #pragma unroll
  for (int mt = 0; mt < 4; mt++) {
    int r0 = rowB + mBase + mt*16 + gid;
    #pragma unroll
    for (int nt = 0; nt < 4; nt++) {
      int c0 = colB + nBase + nt*8 + tig*2;
      float b0 = bias[c0], b1 = bias[c0+1];
      float v0 = acc[mt][nt][0] + b0;
      float v1 = acc[mt][nt][1] + b1;
      float v2 = acc[mt][nt][2] + b0;
      float v3 = acc[mt][nt][3] + b1;
      if (RELU) { v0 = fmaxf(v0,0.f); v1 = fmaxf(v1,0.f); v2 = fmaxf(v2,0.f); v3 = fmaxf(v3,0.f); }
      float2 lo = make_float2(v0, v1);
      float2 hi = make_float2(v2, v3);
      *(float2*)(C + (size_t)r0*N + c0) = lo;
      *(float2*)(C + (size_t)(r0+8)*N + c0) = hi;
    }
  }
}

// ------------------------- attention ------------------------------------------
__global__ void attn_scores_kernel(const float* __restrict__ QKV, float* __restrict__ S) {
  const int bnh = blockIdx.z, bn = bnh >> 3, h = bnh & 7;
  const float* Qp = QKV + (size_t)bn*DSEQ*768 + h*HSZ;
  const float* Kp = Qp + HDIM;
  __shared__ float Qs[32][65];
  __shared__ float Ks[32][65];
  const int tx = threadIdx.x, ty = threadIdx.y;
  const int tid = ty*16+tx;
  const int q0 = blockIdx.y*64, k0 = blockIdx.x*64;
  #pragma unroll
  for (int i = 0; i < 8; i++) {
    int idx = tid + i*256;
    int m = idx >> 5, kk = idx & 31;
    Qs[kk][m] = Qp[(size_t)(q0+m)*768 + kk];
    Ks[kk][m] = Kp[(size_t)(k0+m)*768 + kk];
  }
  __syncthreads();
  float acc[4][4] = {};
  #pragma unroll 8
  for (int k = 0; k < 32; k++) {
    float a[4], bv[4];
    #pragma unroll
    for (int i = 0; i < 4; i++) a[i] = Qs[k][ty*4+i];
    #pragma unroll
    for (int j = 0; j < 4; j++) bv[j] = Ks[k][tx*4+j];
    #pragma unroll
    for (int i = 0; i < 4; i++)
      #pragma unroll
      for (int j = 0; j < 4; j++)
        acc[i][j] = fmaf(a[i], bv[j], acc[i][j]);
  }
  float* Sp = S + (size_t)bnh*DSEQ*DSEQ;
  const float scale = 0.17677669529663687f;  // 1/sqrt(32)
  #pragma unroll
  for (int i = 0; i < 4; i++)
    #pragma unroll
    for (int j = 0; j < 4; j++)
      Sp[(size_t)(q0+ty*4+i)*DSEQ + k0+tx*4+j] = acc[i][j]*scale;
}

__global__ void softmax_kernel(float* __restrict__ S, const float* __restrict__ mask_d) {
  int row = blockIdx.x*8 + (threadIdx.x >> 5);     // bnh*512 + q
  int lane = threadIdx.x & 31;
  int bn = row >> 12;
  float* Sp = S + (size_t)row*DSEQ;
  const float* mp = mask_d + bn*DSEQ;
  float v[16]; float mx = -1e30f;
  #pragma unroll
  for (int i = 0; i < 16; i++) {
    int k = lane + i*32;
    float x = (mp[k] > 0.f) ? Sp[k] : -1e9f;
    v[i] = x; mx = fmaxf(mx, x);
  }
  #pragma unroll
  for (int off = 16; off; off >>= 1) mx = fmaxf(mx, __shfl_xor_sync(0xffffffffu, mx, off));
  float sum = 0.f;
  #pragma unroll
  for (int i = 0; i < 16; i++) { v[i] = __expf(v[i] - mx); sum += v[i]; }
  #pragma unroll
  for (int off = 16; off; off >>= 1) sum += __shfl_xor_sync(0xffffffffu, sum, off);
  float inv = 1.f / sum;
  #pragma unroll
  for (int i = 0; i < 16; i++) Sp[lane + i*32] = v[i]*inv;
}

__global__ void attn_pv_kernel(const float* __restrict__ S, const float* __restrict__ QKV,
                               float* __restrict__ O) {
  const int bnh = blockIdx.y, bn = bnh >> 3, h = bnh & 7;
  const int q0 = blockIdx.x*64;
  const float* Sp = S + (size_t)bnh*DSEQ*DSEQ;
  const float* Vp = QKV + (size_t)bn*DSEQ*768 + 2*HDIM + h*HSZ;
  __shared__ float Ps[32][65];
  __shared__ float Vs[32][33];
  const int tx = threadIdx.x, ty = threadIdx.y;
  const int tid = ty*16+tx;
  float acc[4][2] = {};
  for (int kt = 0; kt < DSEQ; kt += 32) {
    #pragma unroll
    for (int i = 0; i < 8; i++) {
      int idx = tid + i*256; int m = idx >> 5, k = idx & 31;
      Ps[k][m] = Sp[(size_t)(q0+m)*DSEQ + kt + k];
    }
    #pragma unroll
    for (int i = 0; i < 4; i++) {
      int idx = tid + i*256; int k = idx >> 5, n = idx & 31;
      Vs[k][n] = Vp[(size_t)(kt+k)*768 + n];
    }
    __syncthreads();
    #pragma unroll 8
    for (int k = 0; k < 32; k++) {
      float b0 = Vs[k][tx*2], b1 = Vs[k][tx*2+1];
      #pragma unroll
      for (int i = 0; i < 4; i++) {
        float a = Ps[k][ty*4+i];
        acc[i][0] = fmaf(a, b0, acc[i][0]);
        acc[i][1] = fmaf(a, b1, acc[i][1]);
      }
    }
    __syncthreads();
  }
  #pragma unroll
  for (int i = 0; i < 4; i++)
    #pragma unroll
    for (int j = 0; j < 2; j++)
      O[(size_t)(bn*DSEQ + q0 + ty*4 + i)*HDIM + h*HSZ + tx*2 + j] = acc[i][j];
}

// ------------------------- residual + LayerNorm --------------------------------
__global__ void add_ln_kernel(const float* __restrict__ Xin, const float* __restrict__ Y,
                              const float* __restrict__ g, const float* __restrict__ b,
                              float* __restrict__ Out) {
  __shared__ float red[256];
  int row = blockIdx.x, tid = threadIdx.x;
  float v = Xin[(size_t)row*HDIM + tid] + Y[(size_t)row*HDIM + tid];
  red[tid] = v; __syncthreads();
  for (int s = 128; s > 0; s >>= 1) { if (tid < s) red[tid] += red[tid+s]; __syncthreads(); }
  float mean = red[0] * (1.f/HDIM);
  __syncthreads();
  float dv = v - mean;
  red[tid] = dv*dv; __syncthreads();
  for (int s = 128; s > 0; s >>= 1) { if (tid < s) red[tid] += red[tid+s]; __syncthreads(); }
  float var = red[0] * (1.f/HDIM);
  Out[(size_t)row*HDIM + tid] = dv * rsqrtf(var + 1e-5f) * g[tid] + b[tid];
}

// ------------------------- cosine head ------------------------------------------
__global__ void rownorm_kernel(const float* __restrict__ In, float* __restrict__ Out) {
  __shared__ float red[256];
  int row = blockIdx.x, tid = threadIdx.x;
  float v = In[(size_t)row*HDIM + tid];
  red[tid] = v*v; __syncthreads();
  for (int s=128; s>0; s>>=1){ if(tid<s) red[tid]+=red[tid+s]; __syncthreads(); }
  float n = fmaxf(sqrtf(red[0]), 1e-8f);
  Out[(size_t)row*HDIM + tid] = v / n;
}

__global__ void dc_norm_kernel(const int* __restrict__ dtok, const float* __restrict__ embw,
                               const float* __restrict__ Xf, const float* __restrict__ wc,
                               const float* __restrict__ bc, float* __restrict__ DN) {
  __shared__ float red[256];
  int row = blockIdx.x, tid = threadIdx.x;
  float de = embw[(size_t)dtok[row]*HDIM + tid];
  float v = wc[0]*de + wc[1]*Xf[(size_t)row*HDIM + tid] + bc[0];
  red[tid] = v*v; __syncthreads();
  for (int s=128;s>0;s>>=1){ if(tid<s) red[tid]+=red[tid+s]; __syncthreads(); }
  float n = fmaxf(sqrtf(red[0]), 1e-8f);
  DN[(size_t)row*HDIM + tid] = v / n;
}

__global__ void cos_kernel(const float* __restrict__ QN, const float* __restrict__ DN,
                           float* __restrict__ COS) {
  __shared__ float Qs[NQ*HDIM];
  int bn = blockIdx.y;
  int b = bn >> 1;
  int t = blockIdx.x*128 + threadIdx.x;
  for (int i = threadIdx.x; i < NQ*HDIM; i += 128) Qs[i] = QN[(size_t)b*NQ*HDIM + i];
  __syncthreads();
  const float* dp = DN + ((size_t)bn*DSEQ + t)*HDIM;
  float acc[NQ] = {};
  for (int hh = 0; hh < HDIM; hh++) {
    float dv = dp[hh];
    #pragma unroll
    for (int qq = 0; qq < NQ; qq++) acc[qq] = fmaf(dv, Qs[qq*HDIM+hh], acc[qq]);
  }
  #pragma unroll
  for (int qq = 0; qq < NQ; qq++)
    COS[((size_t)bn*NQ + qq)*DSEQ + t] = acc[qq];
}

// ------------------------- RBF pooling + MLP ------------------------------------
__global__ void rbf_y_kernel(const float* __restrict__ COS, const float* __restrict__ mask_d,
                             float* __restrict__ Y) {
  size_t idx = (size_t)blockIdx.x*256 + threadIdx.x;
  int k = (int)(idx & (KRBF-1));
  int row = (int)(idx >> 7);
  int dp = row % DPOOL;
  int bq = row / DPOOL;
  int bn = bq >> 4;
  const float* cr = COS + (size_t)bq*DSEQ + dp*2;
  const float* mr = mask_d + bn*DSEQ + dp*2;
  float mu = 1.f - (float)k*(2.f/KRBF);
  float s = 0.f;
  #pragma unroll
  for (int j = 0; j < 4; j++) {
    float c = cr[j] - mu;
    s += mr[j]*__expf(-50.f*c*c);
  }
  Y[idx] = __logf(s + 1e-6f);
}

__global__ void rbf_s_kernel(const float* __restrict__ Hm, const float* __restrict__ w2,
                             const float* __restrict__ b2, float* __restrict__ SV) {
  int row = blockIdx.x*8 + (threadIdx.x>>5);
  int lane = threadIdx.x & 31;
  const float* hp = Hm + (size_t)row*HDIM;
  float acc = 0.f;
  #pragma unroll
  for (int i = 0; i < 8; i++) acc = fmaf(hp[lane + i*32], w2[lane + i*32], acc);
  for (int off=16; off; off>>=1) acc += __shfl_xor_sync(0xffffffffu, acc, off);
  if (lane==0) SV[row] = acc + b2[0];
}

__global__ void final_max_kernel(const float* __restrict__ SV, float* __restrict__ SC) {
  __shared__ float red[256];
  int bq = blockIdx.x, tid = threadIdx.x;
  float mx = (tid < DPOOL) ? SV[(size_t)bq*DPOOL + tid] : -1e30f;
  red[tid] = mx; __syncthreads();
  for (int s=128;s>0;s>>=1){ if(tid<s) red[tid]=fmaxf(red[tid],red[tid+s]); __syncthreads(); }
  if (tid==0) SC[bq] = red[0];
}

__global__ void final_sum_kernel(const float* __restrict__ SC, const float* __restrict__ mask_q,
                                 float* __restrict__ out) {
  int bn = threadIdx.x;       // 32
  int b = bn >> 1;
  float s = 0.f;
  #pragma unroll
  for (int qq = 0; qq < NQ; qq++)
    s += SC[bn*NQ + qq] * mask_q[b*NQ + qq];
  out[bn] = s;
}

// ------------------------- launcher ---------------------------------------------
extern "C" void kernel_launch(void* const* d_in, const int* in_sizes, int n_in,
                              void* d_out, int out_size) {
  const int*   qtok     = (const int*)d_in[0];
  const int*   dtok     = (const int*)d_in[1];
  const float* mask_q   = (const float*)d_in[2];
  const float* mask_d   = (const float*)d_in[3];
  const float* embw     = (const float*)d_in[4];
  const float* fc_qt_w  = (const float*)d_in[5];
  const float* fc_qt_b  = (const float*)d_in[6];
  const float* qkv_w    = (const float*)d_in[7];
  const float* qkv_b    = (const float*)d_in[8];
  const float* out_w    = (const float*)d_in[9];
  const float* out_b    = (const float*)d_in[10];
  const float* ln1_g    = (const float*)d_in[11];
  const float* ln1_b    = (const float*)d_in[12];
  const float* w1       = (const float*)d_in[13];
  const float* b1       = (const float*)d_in[14];
  const float* w2       = (const float*)d_in[15];
  const float* b2       = (const float*)d_in[16];
  const float* ln2_g    = (const float*)d_in[17];
  const float* ln2_b    = (const float*)d_in[18];
  const float* fc_ctx_w = (const float*)d_in[19];
  const float* fc_ctx_b = (const float*)d_in[20];
  const float* rb1w     = (const float*)d_in[21];
  const float* rb1b     = (const float*)d_in[22];
  const float* rb2w     = (const float*)d_in[23];
  const float* rb2b     = (const float*)d_in[24];
  float* out = (float*)d_out;

  void* p;
  cudaGetSymbolAddress(&p, g_X);   float* X   = (float*)p;
  cudaGetSymbolAddress(&p, g_T);   float* T   = (float*)p;
  cudaGetSymbolAddress(&p, g_FF);  float* FF  = (float*)p;
  cudaGetSymbolAddress(&p, g_QKV); float* QKV = (float*)p;
  cudaGetSymbolAddress(&p, g_S);   float* S   = (float*)p;
  cudaGetSymbolAddress(&p, g_O);   float* O   = (float*)p;
  cudaGetSymbolAddress(&p, g_QE);  float* QE  = (float*)p;
  cudaGetSymbolAddress(&p, g_QT);  float* QT  = (float*)p;
  cudaGetSymbolAddress(&p, g_QN);  float* QN  = (float*)p;
  cudaGetSymbolAddress(&p, g_DN);  float* DN  = (float*)p;
  cudaGetSymbolAddress(&p, g_COS); float* COS = (float*)p;
  cudaGetSymbolAddress(&p, g_YR);  float* YR  = (float*)p;
  cudaGetSymbolAddress(&p, g_HR);  float* HR  = (float*)p;
  cudaGetSymbolAddress(&p, g_SV);  float* SV  = (float*)p;
  cudaGetSymbolAddress(&p, g_SC);  float* SC  = (float*)p;

  dim3 blk(16,16);

  embed_doc_kernel<<<NROWS*HDIM/256, 256>>>(dtok, embw, X);

  for (int l = 0; l < NLAYER; l++) {
    gemm_tf32_kernel<false><<<dim3(768/128, NROWS/128), 256>>>(
        X, qkv_w + (size_t)l*HDIM*768, qkv_b + l*768, QKV, NROWS, 768, HDIM);
    attn_scores_kernel<<<dim3(8,8,NSEQ*NHEAD), blk>>>(QKV, S);
    softmax_kernel<<<NSEQ*NHEAD*DSEQ/8, 256>>>(S, mask_d);
    attn_pv_kernel<<<dim3(8,NSEQ*NHEAD), blk>>>(S, QKV, O);
    gemm_tf32_kernel<false><<<dim3(2, NROWS/128), 256>>>(
        O, out_w + (size_t)l*HDIM*HDIM, out_b + l*HDIM, T, NROWS, HDIM, HDIM);
    add_ln_kernel<<<NROWS,256>>>(X, T, ln1_g+l*HDIM, ln1_b+l*HDIM, X);
    gemm_tf32_kernel<true><<<dim3(2, NROWS/128), 256>>>(
        X, w1 + (size_t)l*HDIM*HDIM, b1 + l*HDIM, FF, NROWS, HDIM, HDIM);
    gemm_tf32_kernel<false><<<dim3(2, NROWS/128), 256>>>(
        FF, w2 + (size_t)l*HDIM*HDIM, b2 + l*HDIM, T, NROWS, HDIM, HDIM);
    add_ln_kernel<<<NROWS,256>>>(X, T, ln2_g+l*HDIM, ln2_b+l*HDIM, X);
  }

  embed_q_kernel<<<NQROWS*HDIM/256,256>>>(qtok, embw, QE);
  gemm_tf32_kernel<false><<<dim3(2, NQROWS/128), 256>>>(QE, fc_qt_w, fc_qt_b, QT, NQROWS, HDIM, HDIM);
  rownorm_kernel<<<NQROWS,256>>>(QT, QN);
  dc_norm_kernel<<<NROWS,256>>>(dtok, embw, X, fc_ctx_w, fc_ctx_b, DN);
  cos_kernel<<<dim3(DSEQ/128, NSEQ),128>>>(QN, DN, COS);

  rbf_y_kernel<<<NRBFROWS*KRBF/256, 256>>>(COS, mask_d, YR);
  gemm_tf32_kernel<true><<<dim3(2, NRBFROWS/128), 256>>>(YR, rb1w, rb1b, HR, NRBFROWS, HDIM, KRBF);
  rbf_s_kernel<<<NRBFROWS/8, 256>>>(HR, rb2w, rb2b, SV);
  final_max_kernel<<<NBQ,256>>>(SV, SC);
  final_sum_kernel<<<1,32>>>(SC, mask_q, out);
}

// round 3
// speedup vs baseline: 2.5879x; 1.7767x over previous
#include <cuda_runtime.h>
#include <math.h>
#include <stdint.h>

#define NB 16
#define NDOC 2
#define NQ 16
#define DSEQ 512
#define HDIM 256
#define NHEAD 8
#define HSZ 32
#define NLAYER 2
#define KRBF 128
#define DPOOL 255
#define NSEQ (NB*NDOC)          // 32
#define NROWS (NSEQ*DSEQ)       // 16384
#define NQROWS (NB*NQ)          // 256
#define NBQ (NSEQ*NQ)           // 512
#define NRBFROWS (NBQ*DPOOL)    // 130560

// ------------------------- scratch (static device, no allocs) -------------------
__device__ float g_X[NROWS*HDIM];
__device__ float g_T[NROWS*HDIM];
__device__ float g_FF[NROWS*HDIM];
__device__ float g_QKV[NROWS*3*HDIM];
__device__ float g_O[NROWS*HDIM];
__device__ float g_QE[NQROWS*HDIM];
__device__ float g_QT[NQROWS*HDIM];
__device__ float g_QN[NQROWS*HDIM];
__device__ float g_DN[NROWS*HDIM];
__device__ float g_COS[NBQ*DSEQ];
__device__ float g_YR[(size_t)NRBFROWS*KRBF];
__device__ float g_HR[(size_t)NRBFROWS*HDIM];
__device__ float g_SV[NRBFROWS];
__device__ float g_SC[NBQ];

// ------------------------- embedding + positional encoding ---------------------
__global__ void embed_doc_kernel(const int* __restrict__ dtok, const float* __restrict__ embw,
                                 float* __restrict__ X) {
  int idx = blockIdx.x*256 + threadIdx.x;
  int h = idx & (HDIM-1);
  int row = idx >> 8;              // bn*512 + t
  int t = row & (DSEQ-1);
  int tok = dtok[row];
  int i = h >> 1;
  float div = expf((float)i * -0.07195578415606394f);   // exp(2i * -ln(10000)/256)
  float ang = (float)t * div;
  float pe = (h & 1) ? cosf(ang) : sinf(ang);
  X[idx] = embw[(size_t)tok*HDIM + h] + pe;
}

__global__ void embed_q_kernel(const int* __restrict__ qtok, const float* __restrict__ embw,
                               float* __restrict__ QE) {
  int idx = blockIdx.x*256 + threadIdx.x;
  int h = idx & (HDIM-1), row = idx >> 8;
  QE[idx] = embw[(size_t)qtok[row]*HDIM + h];
}

// ------------------------- tf32 helpers ----------------------------------------
__device__ __forceinline__ float to_tf32(float x) {
  uint32_t u;
  asm("cvt.rna.tf32.f32 %0, %1;" : "=r"(u) : "f"(x));
  return __uint_as_float(u);
}

__device__ __forceinline__ void mma_tf32(float* c, const float* a, const float* b) {
  asm volatile(
    "mma.sync.aligned.m16n8k8.row.col.f32.tf32.tf32.f32 "
    "{%0,%1,%2,%3}, {%4,%5,%6,%7}, {%8,%9}, {%0,%1,%2,%3};"
    : "+f"(c[0]), "+f"(c[1]), "+f"(c[2]), "+f"(c[3])
    : "r"(__float_as_uint(a[0])), "r"(__float_as_uint(a[1])),
      "r"(__float_as_uint(a[2])), "r"(__float_as_uint(a[3])),
      "r"(__float_as_uint(b[0])), "r"(__float_as_uint(b[1])));
}

// ------------------------- tf32 tensor-core GEMM: C = A@B + bias ----------------
template<bool RELU>
__global__ void __launch_bounds__(256)
gemm_tf32_kernel(const float* __restrict__ A, const float* __restrict__ Bm,
                 const float* __restrict__ bias, float* __restrict__ C,
                 int M, int N, int Kd) {
  __shared__ float As[128][20];
  __shared__ float Bs[16][136];

  const int tid = threadIdx.x;
  const int warp = tid >> 5, lane = tid & 31;
  const int gid = lane >> 2, tig = lane & 3;
  const int warpM = warp >> 2, warpN = warp & 3;   // 2 x 4 warp grid
  const int mBase = warpM*64, nBase = warpN*32;
  const int rowB = blockIdx.y*128, colB = blockIdx.x*128;

  float acc[4][4][4];
  #pragma unroll
  for (int i = 0; i < 4; i++)
    #pragma unroll
    for (int j = 0; j < 4; j++)
      #pragma unroll
      for (int k = 0; k < 4; k++) acc[i][j][k] = 0.f;

  for (int kt = 0; kt < Kd; kt += 16) {
    #pragma unroll
    for (int it = 0; it < 2; it++) {
      int slot = tid + it*256;
      int r = slot >> 2, c4 = (slot & 3) << 2;
      float4 v = *(const float4*)(A + (size_t)(rowB + r)*Kd + kt + c4);
      v.x = to_tf32(v.x); v.y = to_tf32(v.y); v.z = to_tf32(v.z); v.w = to_tf32(v.w);
      *(float4*)&As[r][c4] = v;
    }
    #pragma unroll
    for (int it = 0; it < 2; it++) {
      int slot = tid + it*256;
      int kr = slot >> 5, c4 = (slot & 31) << 2;
      float4 v = *(const float4*)(Bm + (size_t)(kt + kr)*N + colB + c4);
      v.x = to_tf32(v.x); v.y = to_tf32(v.y); v.z = to_tf32(v.z); v.w = to_tf32(v.w);
      *(float4*)&Bs[kr][c4] = v;
    }
    __syncthreads();

    #pragma unroll
    for (int ks = 0; ks < 2; ks++) {
      float afr[4][4], bfr[4][2];
      #pragma unroll
      for (int mt = 0; mt < 4; mt++) {
        int r0 = mBase + mt*16 + gid;
        afr[mt][0] = As[r0    ][ks*8 + tig    ];
        afr[mt][1] = As[r0 + 8][ks*8 + tig    ];
        afr[mt][2] = As[r0    ][ks*8 + tig + 4];
        afr[mt][3] = As[r0 + 8][ks*8 + tig + 4];
      }
      #pragma unroll
      for (int nt = 0; nt < 4; nt++) {
        int n0 = nBase + nt*8 + gid;
        bfr[nt][0] = Bs[ks*8 + tig    ][n0];
        bfr[nt][1] = Bs[ks*8 + tig + 4][n0];
      }
      #pragma unroll
      for (int mt = 0; mt < 4; mt++)
        #pragma unroll
        for (int nt = 0; nt < 4; nt++)
          mma_tf32(acc[mt][nt], afr[mt], bfr[nt]);
    }
    __syncthreads();
  }

  #pragma unroll
  for (int mt = 0; mt < 4; mt++) {
    int r0 = rowB + mBase + mt*16 + gid;
    #pragma unroll
    for (int nt = 0; nt < 4; nt++) {
      int c0 = colB + nBase + nt*8 + tig*2;
      float b0 = bias[c0], b1 = bias[c0+1];
      float v0 = acc[mt][nt][0] + b0;
      float v1 = acc[mt][nt][1] + b1;
      float v2 = acc[mt][nt][2] + b0;
      float v3 = acc[mt][nt][3] + b1;
      if (RELU) { v0 = fmaxf(v0,0.f); v1 = fmaxf(v1,0.f); v2 = fmaxf(v2,0.f); v3 = fmaxf(v3,0.f); }
      *(float2*)(C + (size_t)r0*N + c0) = make_float2(v0, v1);
      *(float2*)(C + (size_t)(r0+8)*N + c0) = make_float2(v2, v3);
    }
  }
}

// ------------------------- fused flash attention --------------------------------
// grid (DSEQ/64, NSEQ*NHEAD), 128 threads (4 warps). Warp w handles q rows
// q0 + w*16 .. +15, the full 64-col kv chunk, with online softmax.
__global__ void __launch_bounds__(128)
attn_fused_kernel(const float* __restrict__ QKV, const float* __restrict__ mask_d,
                  float* __restrict__ O) {
  __shared__ float Ks[64][36];
  __shared__ float Vt[32][36];
  __shared__ float Ps[4][16][68];      // warp-private P staging; head aliased as Qs
  __shared__ float ms[64];

  const int bnh = blockIdx.y, bn = bnh >> 3, h = bnh & 7;
  const int q0 = blockIdx.x*64;
  const int tid = threadIdx.x;
  const int warp = tid >> 5, lane = tid & 31;
  const int gid = lane >> 2, tig = lane & 3;
  const float scale = 0.17677669529663687f;  // 1/sqrt(32)

  const float* Qp = QKV + (size_t)bn*DSEQ*768 + h*HSZ;
  const float* Kp = Qp + HDIM;
  const float* Vp = Qp + 2*HDIM;
  const float* mp = mask_d + bn*DSEQ;

  // ---- load Q tile (64x32) into smem (aliased over Ps), read A-fragments ----
  float (*Qs)[36] = (float(*)[36])&Ps[0][0][0];
  #pragma unroll
  for (int i = 0; i < 4; i++) {
    int slot = tid + i*128;               // 512 float4 slots
    int r = slot >> 3, c4 = (slot & 7) << 2;
    float4 v = *(const float4*)(Qp + (size_t)(q0 + r)*768 + c4);
    v.x = to_tf32(v.x); v.y = to_tf32(v.y); v.z = to_tf32(v.z); v.w = to_tf32(v.w);
    *(float4*)&Qs[r][c4] = v;
  }
  __syncthreads();
  float aq[4][4];
  #pragma unroll
  for (int ks = 0; ks < 4; ks++) {
    int r0 = warp*16 + gid;
    aq[ks][0] = Qs[r0    ][ks*8 + tig    ];
    aq[ks][1] = Qs[r0 + 8][ks*8 + tig    ];
    aq[ks][2] = Qs[r0    ][ks*8 + tig + 4];
    aq[ks][3] = Qs[r0 + 8][ks*8 + tig + 4];
  }

  float oacc[4][4] = {};
  float m0 = -1e30f, m1 = -1e30f, l0 = 0.f, l1 = 0.f;

  for (int kc = 0; kc < DSEQ; kc += 64) {
    if (mp[kc] == 0.f) continue;         // prefix mask: whole chunk dead (uniform branch)
    __syncthreads();                      // protect Ks/Vt/Ps from prior-iter readers

    // load K chunk 64x32 -> Ks ; V chunk 64x32 -> Vt (transposed)
    #pragma unroll
    for (int i = 0; i < 4; i++) {
      int slot = tid + i*128;
      int r = slot >> 3, c4 = (slot & 7) << 2;
      float4 kv = *(const float4*)(Kp + (size_t)(kc + r)*768 + c4);
      kv.x = to_tf32(kv.x); kv.y = to_tf32(kv.y); kv.z = to_tf32(kv.z); kv.w = to_tf32(kv.w);
      *(float4*)&Ks[r][c4] = kv;
      float4 vv = *(const float4*)(Vp + (size_t)(kc + r)*768 + c4);
      Vt[c4+0][r] = to_tf32(vv.x); Vt[c4+1][r] = to_tf32(vv.y);
      Vt[c4+2][r] = to_tf32(vv.z); Vt[c4+3][r] = to_tf32(vv.w);
    }
    if (tid < 64) ms[tid] = mp[kc + tid];
    __syncthreads();

    // ---- S = Q K^T (16x64 per warp) ----
    float sacc[8][4];
    #pragma unroll
    for (int nt = 0; nt < 8; nt++)
      #pragma unroll
      for (int k = 0; k < 4; k++) sacc[nt][k] = 0.f;
    #pragma unroll
    for (int ks = 0; ks < 4; ks++) {
      #pragma unroll
      for (int nt = 0; nt < 8; nt++) {
        float b[2];
        b[0] = Ks[nt*8 + gid][ks*8 + tig    ];
        b[1] = Ks[nt*8 + gid][ks*8 + tig + 4];
        mma_tf32(sacc[nt], aq[ks], b);
      }
    }

    // ---- scale + mask + chunk row-max ----
    float mr0 = -1e30f, mr1 = -1e30f;
    #pragma unroll
    for (int nt = 0; nt < 8; nt++) {
      int j0 = nt*8 + tig*2;
      bool v0 = ms[j0] > 0.f, v1 = ms[j0+1] > 0.f;
      sacc[nt][0] = v0 ? sacc[nt][0]*scale : -1e9f;
      sacc[nt][1] = v1 ? sacc[nt][1]*scale : -1e9f;
      sacc[nt][2] = v0 ? sacc[nt][2]*scale : -1e9f;
      sacc[nt][3] = v1 ? sacc[nt][3]*scale : -1e9f;
      mr0 = fmaxf(mr0, fmaxf(sacc[nt][0], sacc[nt][1]));
      mr1 = fmaxf(mr1, fmaxf(sacc[nt][2], sacc[nt][3]));
    }
    #pragma unroll
    for (int off = 1; off <= 2; off <<= 1) {
      mr0 = fmaxf(mr0, __shfl_xor_sync(0xffffffffu, mr0, off));
      mr1 = fmaxf(mr1, __shfl_xor_sync(0xffffffffu, mr1, off));
    }
    float nm0 = fmaxf(m0, mr0), nm1 = fmaxf(m1, mr1);
    float al0 = __expf(m0 - nm0), al1 = __expf(m1 - nm1);
    m0 = nm0; m1 = nm1;

    // ---- P = exp(S - m), stage to smem, accumulate row sums ----
    float sum0 = 0.f, sum1 = 0.f;
    #pragma unroll
    for (int nt = 0; nt < 8; nt++) {
      float p0 = __expf(sacc[nt][0] - nm0);
      float p1 = __expf(sacc[nt][1] - nm0);
      float p2 = __expf(sacc[nt][2] - nm1);
      float p3 = __expf(sacc[nt][3] - nm1);
      sum0 += p0 + p1; sum1 += p2 + p3;
      int j0 = nt*8 + tig*2;
      Ps[warp][gid    ][j0] = to_tf32(p0); Ps[warp][gid    ][j0+1] = to_tf32(p1);
      Ps[warp][gid + 8][j0] = to_tf32(p2); Ps[warp][gid + 8][j0+1] = to_tf32(p3);
    }
    #pragma unroll
    for (int off = 1; off <= 2; off <<= 1) {
      sum0 += __shfl_xor_sync(0xffffffffu, sum0, off);
      sum1 += __shfl_xor_sync(0xffffffffu, sum1, off);
    }
    l0 = l0*al0 + sum0;
    l1 = l1*al1 + sum1;

    // rescale O accumulator
    #pragma unroll
    for (int nt = 0; nt < 4; nt++) {
      oacc[nt][0] *= al0; oacc[nt][1] *= al0;
      oacc[nt][2] *= al1; oacc[nt][3] *= al1;
    }
    __syncwarp();

    // ---- O += P @ V  (A from warp-private Ps, B from Vt) ----
    #pragma unroll
    for (int kt = 0; kt < 8; kt++) {
      float ap[4];
      ap[0] = Ps[warp][gid    ][kt*8 + tig    ];
      ap[1] = Ps[warp][gid + 8][kt*8 + tig    ];
      ap[2] = Ps[warp][gid    ][kt*8 + tig + 4];
      ap[3] = Ps[warp][gid + 8][kt*8 + tig + 4];
      #pragma unroll
      for (int nt = 0; nt < 4; nt++) {
        float b[2];
        b[0] = Vt[nt*8 + gid][kt*8 + tig    ];
        b[1] = Vt[nt*8 + gid][kt*8 + tig + 4];
        mma_tf32(oacc[nt], ap, b);
      }
    }
  }

  // ---- normalize + store ----
  float inv0 = 1.f / l0, inv1 = 1.f / l1;
  int rg0 = bn*DSEQ + q0 + warp*16 + gid;
  #pragma unroll
  for (int nt = 0; nt < 4; nt++) {
    int c0 = h*HSZ + nt*8 + tig*2;
    *(float2*)(O + (size_t)rg0*HDIM + c0)     = make_float2(oacc[nt][0]*inv0, oacc[nt][1]*inv0);
    *(float2*)(O + (size_t)(rg0+8)*HDIM + c0) = make_float2(oacc[nt][2]*inv1, oacc[nt][3]*inv1);
  }
}

// ------------------------- residual + LayerNorm --------------------------------
__global__ void add_ln_kernel(const float* __restrict__ Xin, const float* __restrict__ Y,
                              const float* __restrict__ g, const float* __restrict__ b,
                              float* __restrict__ Out) {
  __shared__ float red[256];
  int row = blockIdx.x, tid = threadIdx.x;
  float v = Xin[(size_t)row*HDIM + tid] + Y[(size_t)row*HDIM + tid];
  red[tid] = v; __syncthreads();
  for (int s = 128; s > 0; s >>= 1) { if (tid < s) red[tid] += red[tid+s]; __syncthreads(); }
  float mean = red[0] * (1.f/HDIM);
  __syncthreads();
  float dv = v - mean;
  red[tid] = dv*dv; __syncthreads();
  for (int s = 128; s > 0; s >>= 1) { if (tid < s) red[tid] += red[tid+s]; __syncthreads(); }
  float var = red[0] * (1.f/HDIM);
  Out[(size_t)row*HDIM + tid] = dv * rsqrtf(var + 1e-5f) * g[tid] + b[tid];
}

// ------------------------- cosine head ------------------------------------------
__global__ void rownorm_kernel(const float* __restrict__ In, float* __restrict__ Out) {
  __shared__ float red[256];
  int row = blockIdx.x, tid = threadIdx.x;
  float v = In[(size_t)row*HDIM + tid];
  red[tid] = v*v; __syncthreads();
  for (int s=128; s>0; s>>=1){ if(tid<s) red[tid]+=red[tid+s]; __syncthreads(); }
  float n = fmaxf(sqrtf(red[0]), 1e-8f);
  Out[(size_t)row*HDIM + tid] = v / n;
}

__global__ void dc_norm_kernel(const int* __restrict__ dtok, const float* __restrict__ embw,
                               const float* __restrict__ Xf, const float* __restrict__ wc,
                               const float* __restrict__ bc, float* __restrict__ DN) {
  __shared__ float red[256];
  int row = blockIdx.x, tid = threadIdx.x;
  float de = embw[(size_t)dtok[row]*HDIM + tid];
  float v = wc[0]*de + wc[1]*Xf[(size_t)row*HDIM + tid] + bc[0];
  red[tid] = v*v; __syncthreads();
  for (int s=128;s>0;s>>=1){ if(tid<s) red[tid]+=red[tid+s]; __syncthreads(); }
  float n = fmaxf(sqrtf(red[0]), 1e-8f);
  DN[(size_t)row*HDIM + tid] = v / n;
}

__global__ void cos_kernel(const float* __restrict__ QN, const float* __restrict__ DN,
                           float* __restrict__ COS) {
  __shared__ float Qs[NQ*HDIM];
  int bn = blockIdx.y;
  int b = bn >> 1;
  int t = blockIdx.x*128 + threadIdx.x;
  for (int i = threadIdx.x; i < NQ*HDIM; i += 128) Qs[i] = QN[(size_t)b*NQ*HDIM + i];
  __syncthreads();
  const float* dp = DN + ((size_t)bn*DSEQ + t)*HDIM;
  float acc[NQ] = {};
  for (int hh = 0; hh < HDIM; hh++) {
    float dv = dp[hh];
    #pragma unroll
    for (int qq = 0; qq < NQ; qq++) acc[qq] = fmaf(dv, Qs[qq*HDIM+hh], acc[qq]);
  }
  #pragma unroll
  for (int qq = 0; qq < NQ; qq++)
    COS[((size_t)bn*NQ + qq)*DSEQ + t] = acc[qq];
}

// ------------------------- RBF pooling + MLP ------------------------------------
__global__ void rbf_y_kernel(const float* __restrict__ COS, const float* __restrict__ mask_d,
                             float* __restrict__ Y) {
  size_t idx = (size_t)blockIdx.x*256 + threadIdx.x;
  int k = (int)(idx & (KRBF-1));
  int row = (int)(idx >> 7);
  int dp = row % DPOOL;
  int bq = row / DPOOL;
  int bn = bq >> 4;
  const float* cr = COS + (size_t)bq*DSEQ + dp*2;
  const float* mr = mask_d + bn*DSEQ + dp*2;
  float mu = 1.f - (float)k*(2.f/KRBF);
  float s = 0.f;
  #pragma unroll
  for (int j = 0; j < 4; j++) {
    float c = cr[j] - mu;
    s += mr[j]*__expf(-50.f*c*c);
  }
  Y[idx] = __logf(s + 1e-6f);
}

__global__ void rbf_s_kernel(const float* __restrict__ Hm, const float* __restrict__ w2,
                             const float* __restrict__ b2, float* __restrict__ SV) {
  int row = blockIdx.x*8 + (threadIdx.x>>5);
  int lane = threadIdx.x & 31;
  const float* hp = Hm + (size_t)row*HDIM;
  float acc = 0.f;
  #pragma unroll
  for (int i = 0; i < 8; i++) acc = fmaf(hp[lane + i*32], w2[lane + i*32], acc);
  for (int off=16; off; off>>=1) acc += __shfl_xor_sync(0xffffffffu, acc, off);
  if (lane==0) SV[row] = acc + b2[0];
}

__global__ void final_max_kernel(const float* __restrict__ SV, float* __restrict__ SC) {
  __shared__ float red[256];
  int bq = blockIdx.x, tid = threadIdx.x;
  float mx = (tid < DPOOL) ? SV[(size_t)bq*DPOOL + tid] : -1e30f;
  red[tid] = mx; __syncthreads();
  for (int s=128;s>0;s>>=1){ if(tid<s) red[tid]=fmaxf(red[tid],red[tid+s]); __syncthreads(); }
  if (tid==0) SC[bq] = red[0];
}

__global__ void final_sum_kernel(const float* __restrict__ SC, const float* __restrict__ mask_q,
                                 float* __restrict__ out) {
  int bn = threadIdx.x;       // 32
  int b = bn >> 1;
  float s = 0.f;
  #pragma unroll
  for (int qq = 0; qq < NQ; qq++)
    s += SC[bn*NQ + qq] * mask_q[b*NQ + qq];
  out[bn] = s;
}

// ------------------------- launcher ---------------------------------------------
extern "C" void kernel_launch(void* const* d_in, const int* in_sizes, int n_in,
                              void* d_out, int out_size) {
  const int*   qtok     = (const int*)d_in[0];
  const int*   dtok     = (const int*)d_in[1];
  const float* mask_q   = (const float*)d_in[2];
  const float* mask_d   = (const float*)d_in[3];
  const float* embw     = (const float*)d_in[4];
  const float* fc_qt_w  = (const float*)d_in[5];
  const float* fc_qt_b  = (const float*)d_in[6];
  const float* qkv_w    = (const float*)d_in[7];
  const float* qkv_b    = (const float*)d_in[8];
  const float* out_w    = (const float*)d_in[9];
  const float* out_b    = (const float*)d_in[10];
  const float* ln1_g    = (const float*)d_in[11];
  const float* ln1_b    = (const float*)d_in[12];
  const float* w1       = (const float*)d_in[13];
  const float* b1       = (const float*)d_in[14];
  const float* w2       = (const float*)d_in[15];
  const float* b2       = (const float*)d_in[16];
  const float* ln2_g    = (const float*)d_in[17];
  const float* ln2_b    = (const float*)d_in[18];
  const float* fc_ctx_w = (const float*)d_in[19];
  const float* fc_ctx_b = (const float*)d_in[20];
  const float* rb1w     = (const float*)d_in[21];
  const float* rb1b     = (const float*)d_in[22];
  const float* rb2w     = (const float*)d_in[23];
  const float* rb2b     = (const float*)d_in[24];
  float* out = (float*)d_out;

  void* p;
  cudaGetSymbolAddress(&p, g_X);   float* X   = (float*)p;
  cudaGetSymbolAddress(&p, g_T);   float* T   = (float*)p;
  cudaGetSymbolAddress(&p, g_FF);  float* FF  = (float*)p;
  cudaGetSymbolAddress(&p, g_QKV); float* QKV = (float*)p;
  cudaGetSymbolAddress(&p, g_O);   float* O   = (float*)p;
  cudaGetSymbolAddress(&p, g_QE);  float* QE  = (float*)p;
  cudaGetSymbolAddress(&p, g_QT);  float* QT  = (float*)p;
  cudaGetSymbolAddress(&p, g_QN);  float* QN  = (float*)p;
  cudaGetSymbolAddress(&p, g_DN);  float* DN  = (float*)p;
  cudaGetSymbolAddress(&p, g_COS); float* COS = (float*)p;
  cudaGetSymbolAddress(&p, g_YR);  float* YR  = (float*)p;
  cudaGetSymbolAddress(&p, g_HR);  float* HR  = (float*)p;
  cudaGetSymbolAddress(&p, g_SV);  float* SV  = (float*)p;
  cudaGetSymbolAddress(&p, g_SC);  float* SC  = (float*)p;

  embed_doc_kernel<<<NROWS*HDIM/256, 256>>>(dtok, embw, X);

  for (int l = 0; l < NLAYER; l++) {
    gemm_tf32_kernel<false><<<dim3(768/128, NROWS/128), 256>>>(
        X, qkv_w + (size_t)l*HDIM*768, qkv_b + l*768, QKV, NROWS, 768, HDIM);
    attn_fused_kernel<<<dim3(DSEQ/64, NSEQ*NHEAD), 128>>>(QKV, mask_d, O);
    gemm_tf32_kernel<false><<<dim3(2, NROWS/128), 256>>>(
        O, out_w + (size_t)l*HDIM*HDIM, out_b + l*HDIM, T, NROWS, HDIM, HDIM);
    add_ln_kernel<<<NROWS,256>>>(X, T, ln1_g+l*HDIM, ln1_b+l*HDIM, X);
    gemm_tf32_kernel<true><<<dim3(2, NROWS/128), 256>>>(
        X, w1 + (size_t)l*HDIM*HDIM, b1 + l*HDIM, FF, NROWS, HDIM, HDIM);
    gemm_tf32_kernel<false><<<dim3(2, NROWS/128), 256>>>(
        FF, w2 + (size_t)l*HDIM*HDIM, b2 + l*HDIM, T, NROWS, HDIM, HDIM);
    add_ln_kernel<<<NROWS,256>>>(X, T, ln2_g+l*HDIM, ln2_b+l*HDIM, X);
  }

  embed_q_kernel<<<NQROWS*HDIM/256,256>>>(qtok, embw, QE);
  gemm_tf32_kernel<false><<<dim3(2, NQROWS/128), 256>>>(QE, fc_qt_w, fc_qt_b, QT, NQROWS, HDIM, HDIM);
  rownorm_kernel<<<NQROWS,256>>>(QT, QN);
  dc_norm_kernel<<<NROWS,256>>>(dtok, embw, X, fc_ctx_w, fc_ctx_b, DN);
  cos_kernel<<<dim3(DSEQ/128, NSEQ),128>>>(QN, DN, COS);

  rbf_y_kernel<<<NRBFROWS*KRBF/256, 256>>>(COS, mask_d, YR);
  gemm_tf32_kernel<true><<<dim3(2, NRBFROWS/128), 256>>>(YR, rb1w, rb1b, HR, NRBFROWS, HDIM, KRBF);
  rbf_s_kernel<<<NRBFROWS/8, 256>>>(HR, rb2w, rb2b, SV);
  final_max_kernel<<<NBQ,256>>>(SV, SC);
  final_sum_kernel<<<1,32>>>(SC, mask_q, out);
}

// round 6
// speedup vs baseline: 2.8575x; 1.1042x over previous
#include <cuda_runtime.h>
#include <math.h>
#include <stdint.h>

#define NB 16
#define NDOC 2
#define NQ 16
#define DSEQ 512
#define HDIM 256
#define NHEAD 8
#define HSZ 32
#define NLAYER 2
#define KRBF 128
#define DPOOL 255
#define NSEQ (NB*NDOC)          // 32
#define NROWS (NSEQ*DSEQ)       // 16384
#define NQROWS (NB*NQ)          // 256
#define NBQ (NSEQ*NQ)           // 512
#define NRBFROWS (NBQ*DPOOL)    // 130560

// ------------------------- scratch (static device, no allocs) -------------------
__device__ float g_X[NROWS*HDIM];
__device__ float g_T[NROWS*HDIM];
__device__ float g_FF[NROWS*HDIM];
__device__ float g_QKV[NROWS*3*HDIM];
__device__ float g_O[NROWS*HDIM];
__device__ float g_QE[NQROWS*HDIM];
__device__ float g_QT[NQROWS*HDIM];
__device__ float g_QN[NQROWS*HDIM];
__device__ float g_DN[NROWS*HDIM];
__device__ float g_COS[NBQ*DSEQ];
__device__ float g_YR[(size_t)NRBFROWS*KRBF];
__device__ float g_SVP[2*NRBFROWS];
__device__ float g_SC[NBQ];

// ------------------------- embedding + positional encoding ---------------------
__global__ void embed_doc_kernel(const int* __restrict__ dtok, const float* __restrict__ embw,
                                 float* __restrict__ X) {
  int idx = blockIdx.x*256 + threadIdx.x;
  int h = idx & (HDIM-1);
  int row = idx >> 8;              // bn*512 + t
  int t = row & (DSEQ-1);
  int tok = dtok[row];
  int i = h >> 1;
  float div = expf((float)i * -0.07195578415606394f);
  float ang = (float)t * div;
  float pe = (h & 1) ? cosf(ang) : sinf(ang);
  X[idx] = embw[(size_t)tok*HDIM + h] + pe;
}

__global__ void embed_q_kernel(const int* __restrict__ qtok, const float* __restrict__ embw,
                               float* __restrict__ QE) {
  int idx = blockIdx.x*256 + threadIdx.x;
  int h = idx & (HDIM-1), row = idx >> 8;
  QE[idx] = embw[(size_t)qtok[row]*HDIM + h];
}

// ------------------------- tf32 helpers ----------------------------------------
__device__ __forceinline__ float to_tf32(float x) {
  uint32_t u;
  asm("cvt.rna.tf32.f32 %0, %1;" : "=r"(u) : "f"(x));
  return __uint_as_float(u);
}

__device__ __forceinline__ void mma_tf32(float* c, const float* a, const float* b) {
  asm volatile(
    "mma.sync.aligned.m16n8k8.row.col.f32.tf32.tf32.f32 "
    "{%0,%1,%2,%3}, {%4,%5,%6,%7}, {%8,%9}, {%0,%1,%2,%3};"
    : "+f"(c[0]), "+f"(c[1]), "+f"(c[2]), "+f"(c[3])
    : "r"(__float_as_uint(a[0])), "r"(__float_as_uint(a[1])),
      "r"(__float_as_uint(a[2])), "r"(__float_as_uint(a[3])),
      "r"(__float_as_uint(b[0])), "r"(__float_as_uint(b[1])));
}

__device__ __forceinline__ void cp16(uint32_t s, const void* g) {
  asm volatile("cp.async.cg.shared.global [%0], [%1], 16;\n" :: "r"(s), "l"(g));
}
__device__ __forceinline__ uint32_t saddr(const void* p) {
  return (uint32_t)__cvta_generic_to_shared(p);
}
#define CP_COMMIT() asm volatile("cp.async.commit_group;\n" ::: "memory")
#define CP_WAIT0()  asm volatile("cp.async.wait_group 0;\n" ::: "memory")

// ------------------------- mainloop body (shared by the two GEMM kernels) -------
// As[2][128][20], Bs[2][16][136]; 128x128 block tile, 2x4 warps of 64x32.
// As/Bs are alignas(16): cp.async.cg requires 16B-aligned smem dst.
#define GEMM_LOAD_TILE(st, kt)                                                  \
  do {                                                                          \
    _Pragma("unroll")                                                           \
    for (int it = 0; it < 2; it++) {                                            \
      int slot = tid + it*256;                                                  \
      int r = slot >> 2, c4 = (slot & 3) << 2;                                  \
      cp16(saddr(&As[st][r][c4]), A + (size_t)(rowB + r)*Kd + (kt) + c4);       \
    }                                                                           \
    _Pragma("unroll")                                                           \
    for (int it = 0; it < 2; it++) {                                            \
      int slot = tid + it*256;                                                  \
      int kr = slot >> 5, c4 = (slot & 31) << 2;                                \
      cp16(saddr(&Bs[st][kr][c4]), Bm + (size_t)((kt) + kr)*N + colB + c4);     \
    }                                                                           \
  } while (0)

#define GEMM_COMPUTE_TILE(st)                                                   \
  do {                                                                          \
    _Pragma("unroll")                                                           \
    for (int ks = 0; ks < 2; ks++) {                                            \
      float afr[4][4], bfr[4][2];                                               \
      _Pragma("unroll")                                                         \
      for (int mt = 0; mt < 4; mt++) {                                          \
        int r0 = mBase + mt*16 + gid;                                           \
        afr[mt][0] = As[st][r0    ][ks*8 + tig    ];                            \
        afr[mt][1] = As[st][r0 + 8][ks*8 + tig    ];                            \
        afr[mt][2] = As[st][r0    ][ks*8 + tig + 4];                            \
        afr[mt][3] = As[st][r0 + 8][ks*8 + tig + 4];                            \
      }                                                                         \
      _Pragma("unroll")                                                         \
      for (int nt = 0; nt < 4; nt++) {                                          \
        int n0 = nBase + nt*8 + gid;                                            \
        bfr[nt][0] = Bs[st][ks*8 + tig    ][n0];                                \
        bfr[nt][1] = Bs[st][ks*8 + tig + 4][n0];                                \
      }                                                                         \
      _Pragma("unroll")                                                         \
      for (int mt = 0; mt < 4; mt++)                                            \
        _Pragma("unroll")                                                       \
        for (int nt = 0; nt < 4; nt++)                                          \
          mma_tf32(acc[mt][nt], afr[mt], bfr[nt]);                              \
    }                                                                           \
  } while (0)

#define GEMM_MAINLOOP()                                                         \
  GEMM_LOAD_TILE(0, 0); CP_COMMIT(); CP_WAIT0(); __syncthreads();               \
  {                                                                             \
    int cur = 0;                                                                \
    for (int kt = 0; kt < Kd; kt += 16) {                                       \
      int nxt = kt + 16;                                                        \
      if (nxt < Kd) { GEMM_LOAD_TILE(cur ^ 1, nxt); CP_COMMIT(); }              \
      GEMM_COMPUTE_TILE(cur);                                                   \
      if (nxt < Kd) CP_WAIT0();                                                 \
      __syncthreads();                                                          \
      cur ^= 1;                                                                 \
    }                                                                           \
  }

// ------------------------- tf32 tensor-core GEMM: C = A@B + bias ----------------
template<bool RELU>
__global__ void __launch_bounds__(256)
gemm_tf32_kernel(const float* __restrict__ A, const float* __restrict__ Bm,
                 const float* __restrict__ bias, float* __restrict__ C,
                 int M, int N, int Kd) {
  __shared__ alignas(16) float As[2][128][20];
  __shared__ alignas(16) float Bs[2][16][136];

  const int tid = threadIdx.x;
  const int warp = tid >> 5, lane = tid & 31;
  const int gid = lane >> 2, tig = lane & 3;
  const int warpM = warp >> 2, warpN = warp & 3;
  const int mBase = warpM*64, nBase = warpN*32;
  const int rowB = blockIdx.y*128, colB = blockIdx.x*128;

  float acc[4][4][4];
  #pragma unroll
  for (int i = 0; i < 4; i++)
    #pragma unroll
    for (int j = 0; j < 4; j++)
      #pragma unroll
      for (int k = 0; k < 4; k++) acc[i][j][k] = 0.f;

  GEMM_MAINLOOP();

  #pragma unroll
  for (int mt = 0; mt < 4; mt++) {
    int r0 = rowB + mBase + mt*16 + gid;
    #pragma unroll
    for (int nt = 0; nt < 4; nt++) {
      int c0 = colB + nBase + nt*8 + tig*2;
      float b0 = bias[c0], b1 = bias[c0+1];
      float v0 = acc[mt][nt][0] + b0;
      float v1 = acc[mt][nt][1] + b1;
      float v2 = acc[mt][nt][2] + b0;
      float v3 = acc[mt][nt][3] + b1;
      if (RELU) { v0 = fmaxf(v0,0.f); v1 = fmaxf(v1,0.f); v2 = fmaxf(v2,0.f); v3 = fmaxf(v3,0.f); }
      *(float2*)(C + (size_t)r0*N + c0) = make_float2(v0, v1);
      *(float2*)(C + (size_t)(r0+8)*N + c0) = make_float2(v2, v3);
    }
  }
}

// ------------------------- RBF fc1 GEMM with fused relu + fc2 reduce ------------
// h = relu(Y@W1[:,colB:colB+128] + b1); s_partial = h . w2[colB:colB+128].
// Per-warp 32-col partials are reduced across warpN via smem (no cross-warp
// races), one value per row written to SVp[chunk]. Chunks summed in final_max.
__global__ void __launch_bounds__(256)
gemm_rbf_fused_kernel(const float* __restrict__ A, const float* __restrict__ Bm,
                      const float* __restrict__ bias, const float* __restrict__ w2g,
                      float* __restrict__ SVp) {
  __shared__ alignas(16) float As[2][128][20];
  __shared__ alignas(16) float Bs[2][16][136];
  __shared__ float part[4][128];

  const int N = HDIM, Kd = KRBF;
  const int tid = threadIdx.x;
  const int warp = tid >> 5, lane = tid & 31;
  const int gid = lane >> 2, tig = lane & 3;
  const int warpM = warp >> 2, warpN = warp & 3;
  const int mBase = warpM*64, nBase = warpN*32;
  const int rowB = blockIdx.y*128, colB = blockIdx.x*128;

  float acc[4][4][4];
  #pragma unroll
  for (int i = 0; i < 4; i++)
    #pragma unroll
    for (int j = 0; j < 4; j++)
      #pragma unroll
      for (int k = 0; k < 4; k++) acc[i][j][k] = 0.f;

  GEMM_MAINLOOP();

  float p0[4] = {0.f,0.f,0.f,0.f}, p1[4] = {0.f,0.f,0.f,0.f};
  #pragma unroll
  for (int mt = 0; mt < 4; mt++) {
    #pragma unroll
    for (int nt = 0; nt < 4; nt++) {
      int c0 = colB + nBase + nt*8 + tig*2;
      float b0 = bias[c0], b1 = bias[c0+1];
      float w0 = w2g[c0], w1 = w2g[c0+1];
      float v0 = fmaxf(acc[mt][nt][0] + b0, 0.f);
      float v1 = fmaxf(acc[mt][nt][1] + b1, 0.f);
      float v2 = fmaxf(acc[mt][nt][2] + b0, 0.f);
      float v3 = fmaxf(acc[mt][nt][3] + b1, 0.f);
      p0[mt] += v0*w0 + v1*w1;
      p1[mt] += v2*w0 + v3*w1;
    }
  }
  // sum the 4 tig lanes of each quad -> full 32-col partial for this warp
  #pragma unroll
  for (int mt = 0; mt < 4; mt++) {
    #pragma unroll
    for (int off = 1; off <= 2; off <<= 1) {
      p0[mt] += __shfl_xor_sync(0xffffffffu, p0[mt], off);
      p1[mt] += __shfl_xor_sync(0xffffffffu, p1[mt], off);
    }
    if (tig == 0) {
      int lr = mBase + mt*16 + gid;          // local row 0..127 (warpM splits rows)
      part[warpN][lr]     = p0[mt];
      part[warpN][lr + 8] = p1[mt];
    }
  }
  __syncthreads();
  // sum across the 4 warpN column-groups
  if (tid < 128) {
    float s = part[0][tid] + part[1][tid] + part[2][tid] + part[3][tid];
    SVp[(size_t)blockIdx.x*NRBFROWS + rowB + tid] = s;
  }
}

// ------------------------- fused flash attention --------------------------------
__global__ void __launch_bounds__(128)
attn_fused_kernel(const float* __restrict__ QKV, const float* __restrict__ mask_d,
                  float* __restrict__ O) {
  __shared__ float Ks[64][36];
  __shared__ float Vt[32][36];
  __shared__ float Ps[4][16][68];
  __shared__ float ms[64];

  const int bnh = blockIdx.y, bn = bnh >> 3, h = bnh & 7;
  const int q0 = blockIdx.x*64;
  const int tid = threadIdx.x;
  const int warp = tid >> 5, lane = tid & 31;
  const int gid = lane >> 2, tig = lane & 3;
  const float scale = 0.17677669529663687f;

  const float* Qp = QKV + (size_t)bn*DSEQ*768 + h*HSZ;
  const float* Kp = Qp + HDIM;
  const float* Vp = Qp + 2*HDIM;
  const float* mp = mask_d + bn*DSEQ;

  float (*Qs)[36] = (float(*)[36])&Ps[0][0][0];
  #pragma unroll
  for (int i = 0; i < 4; i++) {
    int slot = tid + i*128;
    int r = slot >> 3, c4 = (slot & 7) << 2;
    float4 v = *(const float4*)(Qp + (size_t)(q0 + r)*768 + c4);
    v.x = to_tf32(v.x); v.y = to_tf32(v.y); v.z = to_tf32(v.z); v.w = to_tf32(v.w);
    *(float4*)&Qs[r][c4] = v;
  }
  __syncthreads();
  float aq[4][4];
  #pragma unroll
  for (int ks = 0; ks < 4; ks++) {
    int r0 = warp*16 + gid;
    aq[ks][0] = Qs[r0    ][ks*8 + tig    ];
    aq[ks][1] = Qs[r0 + 8][ks*8 + tig    ];
    aq[ks][2] = Qs[r0    ][ks*8 + tig + 4];
    aq[ks][3] = Qs[r0 + 8][ks*8 + tig + 4];
  }

  float oacc[4][4] = {};
  float m0 = -1e30f, m1 = -1e30f, l0 = 0.f, l1 = 0.f;

  for (int kc = 0; kc < DSEQ; kc += 64) {
    if (mp[kc] == 0.f) continue;
    __syncthreads();

    #pragma unroll
    for (int i = 0; i < 4; i++) {
      int slot = tid + i*128;
      int r = slot >> 3, c4 = (slot & 7) << 2;
      float4 kv = *(const float4*)(Kp + (size_t)(kc + r)*768 + c4);
      kv.x = to_tf32(kv.x); kv.y = to_tf32(kv.y); kv.z = to_tf32(kv.z); kv.w = to_tf32(kv.w);
      *(float4*)&Ks[r][c4] = kv;
      float4 vv = *(const float4*)(Vp + (size_t)(kc + r)*768 + c4);
      Vt[c4+0][r] = to_tf32(vv.x); Vt[c4+1][r] = to_tf32(vv.y);
      Vt[c4+2][r] = to_tf32(vv.z); Vt[c4+3][r] = to_tf32(vv.w);
    }
    if (tid < 64) ms[tid] = mp[kc + tid];
    __syncthreads();

    float sacc[8][4];
    #pragma unroll
    for (int nt = 0; nt < 8; nt++)
      #pragma unroll
      for (int k = 0; k < 4; k++) sacc[nt][k] = 0.f;
    #pragma unroll
    for (int ks = 0; ks < 4; ks++) {
      #pragma unroll
      for (int nt = 0; nt < 8; nt++) {
        float b[2];
        b[0] = Ks[nt*8 + gid][ks*8 + tig    ];
        b[1] = Ks[nt*8 + gid][ks*8 + tig + 4];
        mma_tf32(sacc[nt], aq[ks], b);
      }
    }

    float mr0 = -1e30f, mr1 = -1e30f;
    #pragma unroll
    for (int nt = 0; nt < 8; nt++) {
      int j0 = nt*8 + tig*2;
      bool v0 = ms[j0] > 0.f, v1 = ms[j0+1] > 0.f;
      sacc[nt][0] = v0 ? sacc[nt][0]*scale : -1e9f;
      sacc[nt][1] = v1 ? sacc[nt][1]*scale : -1e9f;
      sacc[nt][2] = v0 ? sacc[nt][2]*scale : -1e9f;
      sacc[nt][3] = v1 ? sacc[nt][3]*scale : -1e9f;
      mr0 = fmaxf(mr0, fmaxf(sacc[nt][0], sacc[nt][1]));
      mr1 = fmaxf(mr1, fmaxf(sacc[nt][2], sacc[nt][3]));
    }
    #pragma unroll
    for (int off = 1; off <= 2; off <<= 1) {
      mr0 = fmaxf(mr0, __shfl_xor_sync(0xffffffffu, mr0, off));
      mr1 = fmaxf(mr1, __shfl_xor_sync(0xffffffffu, mr1, off));
    }
    float nm0 = fmaxf(m0, mr0), nm1 = fmaxf(m1, mr1);
    float al0 = __expf(m0 - nm0), al1 = __expf(m1 - nm1);
    m0 = nm0; m1 = nm1;

    float sum0 = 0.f, sum1 = 0.f;
    #pragma unroll
    for (int nt = 0; nt < 8; nt++) {
      float p0 = __expf(sacc[nt][0] - nm0);
      float p1 = __expf(sacc[nt][1] - nm0);
      float p2 = __expf(sacc[nt][2] - nm1);
      float p3 = __expf(sacc[nt][3] - nm1);
      sum0 += p0 + p1; sum1 += p2 + p3;
      int j0 = nt*8 + tig*2;
      Ps[warp][gid    ][j0] = to_tf32(p0); Ps[warp][gid    ][j0+1] = to_tf32(p1);
      Ps[warp][gid + 8][j0] = to_tf32(p2); Ps[warp][gid + 8][j0+1] = to_tf32(p3);
    }
    #pragma unroll
    for (int off = 1; off <= 2; off <<= 1) {
      sum0 += __shfl_xor_sync(0xffffffffu, sum0, off);
      sum1 += __shfl_xor_sync(0xffffffffu, sum1, off);
    }
    l0 = l0*al0 + sum0;
    l1 = l1*al1 + sum1;

    #pragma unroll
    for (int nt = 0; nt < 4; nt++) {
      oacc[nt][0] *= al0; oacc[nt][1] *= al0;
      oacc[nt][2] *= al1; oacc[nt][3] *= al1;
    }
    __syncwarp();

    #pragma unroll
    for (int kt = 0; kt < 8; kt++) {
      float ap[4];
      ap[0] = Ps[warp][gid    ][kt*8 + tig    ];
      ap[1] = Ps[warp][gid + 8][kt*8 + tig    ];
      ap[2] = Ps[warp][gid    ][kt*8 + tig + 4];
      ap[3] = Ps[warp][gid + 8][kt*8 + tig + 4];
      #pragma unroll
      for (int nt = 0; nt < 4; nt++) {
        float b[2];
        b[0] = Vt[nt*8 + gid][kt*8 + tig    ];
        b[1] = Vt[nt*8 + gid][kt*8 + tig + 4];
        mma_tf32(oacc[nt], ap, b);
      }
    }
  }

  float inv0 = 1.f / l0, inv1 = 1.f / l1;
  int rg0 = bn*DSEQ + q0 + warp*16 + gid;
  #pragma unroll
  for (int nt = 0; nt < 4; nt++) {
    int c0 = h*HSZ + nt*8 + tig*2;
    *(float2*)(O + (size_t)rg0*HDIM + c0)     = make_float2(oacc[nt][0]*inv0, oacc[nt][1]*inv0);
    *(float2*)(O + (size_t)(rg0+8)*HDIM + c0) = make_float2(oacc[nt][2]*inv1, oacc[nt][3]*inv1);
  }
}

// ------------------------- residual + LayerNorm --------------------------------
__global__ void add_ln_kernel(const float* __restrict__ Xin, const float* __restrict__ Y,
                              const float* __restrict__ g, const float* __restrict__ b,
                              float* __restrict__ Out) {
  __shared__ float red[256];
  int row = blockIdx.x, tid = threadIdx.x;
  float v = Xin[(size_t)row*HDIM + tid] + Y[(size_t)row*HDIM + tid];
  red[tid] = v; __syncthreads();
  for (int s = 128; s > 0; s >>= 1) { if (tid < s) red[tid] += red[tid+s]; __syncthreads(); }
  float mean = red[0] * (1.f/HDIM);
  __syncthreads();
  float dv = v - mean;
  red[tid] = dv*dv; __syncthreads();
  for (int s = 128; s > 0; s >>= 1) { if (tid < s) red[tid] += red[tid+s]; __syncthreads(); }
  float var = red[0] * (1.f/HDIM);
  Out[(size_t)row*HDIM + tid] = dv * rsqrtf(var + 1e-5f) * g[tid] + b[tid];
}

// ------------------------- cosine head ------------------------------------------
__global__ void rownorm_kernel(const float* __restrict__ In, float* __restrict__ Out) {
  __shared__ float red[256];
  int row = blockIdx.x, tid = threadIdx.x;
  float v = In[(size_t)row*HDIM + tid];
  red[tid] = v*v; __syncthreads();
  for (int s=128; s>0; s>>=1){ if(tid<s) red[tid]+=red[tid+s]; __syncthreads(); }
  float n = fmaxf(sqrtf(red[0]), 1e-8f);
  Out[(size_t)row*HDIM + tid] = v / n;
}

__global__ void dc_norm_kernel(const int* __restrict__ dtok, const float* __restrict__ embw,
                               const float* __restrict__ Xf, const float* __restrict__ wc,
                               const float* __restrict__ bc, float* __restrict__ DN) {
  __shared__ float red[256];
  int row = blockIdx.x, tid = threadIdx.x;
  float de = embw[(size_t)dtok[row]*HDIM + tid];
  float v = wc[0]*de + wc[1]*Xf[(size_t)row*HDIM + tid] + bc[0];
  red[tid] = v*v; __syncthreads();
  for (int s=128;s>0;s>>=1){ if(tid<s) red[tid]+=red[tid+s]; __syncthreads(); }
  float n = fmaxf(sqrtf(red[0]), 1e-8f);
  DN[(size_t)row*HDIM + tid] = v / n;
}

__global__ void cos_kernel(const float* __restrict__ QN, const float* __restrict__ DN,
                           float* __restrict__ COS) {
  __shared__ float Qs[NQ*HDIM];
  int bn = blockIdx.y;
  int b = bn >> 1;
  int t = blockIdx.x*128 + threadIdx.x;
  for (int i = threadIdx.x; i < NQ*HDIM; i += 128) Qs[i] = QN[(size_t)b*NQ*HDIM + i];
  __syncthreads();
  const float* dp = DN + ((size_t)bn*DSEQ + t)*HDIM;
  float acc[NQ] = {};
  for (int hh = 0; hh < HDIM; hh++) {
    float dv = dp[hh];
    #pragma unroll
    for (int qq = 0; qq < NQ; qq++) acc[qq] = fmaf(dv, Qs[qq*HDIM+hh], acc[qq]);
  }
  #pragma unroll
  for (int qq = 0; qq < NQ; qq++)
    COS[((size_t)bn*NQ + qq)*DSEQ + t] = acc[qq];
}

// ------------------------- RBF pooling ------------------------------------------
__global__ void rbf_y_kernel(const float* __restrict__ COS, const float* __restrict__ mask_d,
                             float* __restrict__ Y) {
  size_t idx = (size_t)blockIdx.x*256 + threadIdx.x;
  int k = (int)(idx & (KRBF-1));
  int row = (int)(idx >> 7);
  int dp = row % DPOOL;
  int bq = row / DPOOL;
  int bn = bq >> 4;
  const float* cr = COS + (size_t)bq*DSEQ + dp*2;
  const float* mr = mask_d + bn*DSEQ + dp*2;
  float mu = 1.f - (float)k*(2.f/KRBF);
  float s = 0.f;
  #pragma unroll
  for (int j = 0; j < 4; j++) {
    float c = cr[j] - mu;
    s += mr[j]*__expf(-50.f*c*c);
  }
  Y[idx] = __logf(s + 1e-6f);
}

__global__ void final_max_kernel(const float* __restrict__ SVp, const float* __restrict__ b2,
                                 float* __restrict__ SC) {
  __shared__ float red[256];
  int bq = blockIdx.x, tid = threadIdx.x;
  float mx = -1e30f;
  if (tid < DPOOL) {
    size_t r = (size_t)bq*DPOOL + tid;
    mx = SVp[r] + SVp[NRBFROWS + r];
  }
  red[tid] = mx; __syncthreads();
  for (int s=128;s>0;s>>=1){ if(tid<s) red[tid]=fmaxf(red[tid],red[tid+s]); __syncthreads(); }
  if (tid==0) SC[bq] = red[0] + b2[0];
}

__global__ void final_sum_kernel(const float* __restrict__ SC, const float* __restrict__ mask_q,
                                 float* __restrict__ out) {
  int bn = threadIdx.x;       // 32
  int b = bn >> 1;
  float s = 0.f;
  #pragma unroll
  for (int qq = 0; qq < NQ; qq++)
    s += SC[bn*NQ + qq] * mask_q[b*NQ + qq];
  out[bn] = s;
}

// ------------------------- launcher ---------------------------------------------
extern "C" void kernel_launch(void* const* d_in, const int* in_sizes, int n_in,
                              void* d_out, int out_size) {
  const int*   qtok     = (const int*)d_in[0];
  const int*   dtok     = (const int*)d_in[1];
  const float* mask_q   = (const float*)d_in[2];
  const float* mask_d   = (const float*)d_in[3];
  const float* embw     = (const float*)d_in[4];
  const float* fc_qt_w  = (const float*)d_in[5];
  const float* fc_qt_b  = (const float*)d_in[6];
  const float* qkv_w    = (const float*)d_in[7];
  const float* qkv_b    = (const float*)d_in[8];
  const float* out_w    = (const float*)d_in[9];
  const float* out_b    = (const float*)d_in[10];
  const float* ln1_g    = (const float*)d_in[11];
  const float* ln1_b    = (const float*)d_in[12];
  const float* w1       = (const float*)d_in[13];
  const float* b1       = (const float*)d_in[14];
  const float* w2       = (const float*)d_in[15];
  const float* b2       = (const float*)d_in[16];
  const float* ln2_g    = (const float*)d_in[17];
  const float* ln2_b    = (const float*)d_in[18];
  const float* fc_ctx_w = (const float*)d_in[19];
  const float* fc_ctx_b = (const float*)d_in[20];
  const float* rb1w     = (const float*)d_in[21];
  const float* rb1b     = (const float*)d_in[22];
  const float* rb2w     = (const float*)d_in[23];
  const float* rb2b     = (const float*)d_in[24];
  float* out = (float*)d_out;

  void* p;
  cudaGetSymbolAddress(&p, g_X);   float* X   = (float*)p;
  cudaGetSymbolAddress(&p, g_T);   float* T   = (float*)p;
  cudaGetSymbolAddress(&p, g_FF);  float* FF  = (float*)p;
  cudaGetSymbolAddress(&p, g_QKV); float* QKV = (float*)p;
  cudaGetSymbolAddress(&p, g_O);   float* O   = (float*)p;
  cudaGetSymbolAddress(&p, g_QE);  float* QE  = (float*)p;
  cudaGetSymbolAddress(&p, g_QT);  float* QT  = (float*)p;
  cudaGetSymbolAddress(&p, g_QN);  float* QN  = (float*)p;
  cudaGetSymbolAddress(&p, g_DN);  float* DN  = (float*)p;
  cudaGetSymbolAddress(&p, g_COS); float* COS = (float*)p;
  cudaGetSymbolAddress(&p, g_YR);  float* YR  = (float*)p;
  cudaGetSymbolAddress(&p, g_SVP); float* SVp = (float*)p;
  cudaGetSymbolAddress(&p, g_SC);  float* SC  = (float*)p;

  embed_doc_kernel<<<NROWS*HDIM/256, 256>>>(dtok, embw, X);

  for (int l = 0; l < NLAYER; l++) {
    gemm_tf32_kernel<false><<<dim3(768/128, NROWS/128), 256>>>(
        X, qkv_w + (size_t)l*HDIM*768, qkv_b + l*768, QKV, NROWS, 768, HDIM);
    attn_fused_kernel<<<dim3(DSEQ/64, NSEQ*NHEAD), 128>>>(QKV, mask_d, O);
    gemm_tf32_kernel<false><<<dim3(2, NROWS/128), 256>>>(
        O, out_w + (size_t)l*HDIM*HDIM, out_b + l*HDIM, T, NROWS, HDIM, HDIM);
    add_ln_kernel<<<NROWS,256>>>(X, T, ln1_g+l*HDIM, ln1_b+l*HDIM, X);
    gemm_tf32_kernel<true><<<dim3(2, NROWS/128), 256>>>(
        X, w1 + (size_t)l*HDIM*HDIM, b1 + l*HDIM, FF, NROWS, HDIM, HDIM);
    gemm_tf32_kernel<false><<<dim3(2, NROWS/128), 256>>>(
        FF, w2 + (size_t)l*HDIM*HDIM, b2 + l*HDIM, T, NROWS, HDIM, HDIM);
    add_ln_kernel<<<NROWS,256>>>(X, T, ln2_g+l*HDIM, ln2_b+l*HDIM, X);
  }

  embed_q_kernel<<<NQROWS*HDIM/256,256>>>(qtok, embw, QE);
  gemm_tf32_kernel<false><<<dim3(2, NQROWS/128), 256>>>(QE, fc_qt_w, fc_qt_b, QT, NQROWS, HDIM, HDIM);
  rownorm_kernel<<<NQROWS,256>>>(QT, QN);
  dc_norm_kernel<<<NROWS,256>>>(dtok, embw, X, fc_ctx_w, fc_ctx_b, DN);
  cos_kernel<<<dim3(DSEQ/128, NSEQ),128>>>(QN, DN, COS);

  rbf_y_kernel<<<NRBFROWS*KRBF/256, 256>>>(COS, mask_d, YR);
  gemm_rbf_fused_kernel<<<dim3(2, NRBFROWS/128), 256>>>(YR, rb1w, rb1b, rb2w, SVp);
  final_max_kernel<<<NBQ,256>>>(SVp, rb2b, SC);
  final_sum_kernel<<<1,32>>>(SC, mask_q, out);
}

// round 7
// speedup vs baseline: 2.8649x; 1.0026x over previous
#include <cuda_runtime.h>
#include <math.h>
#include <stdint.h>

#define NB 16
#define NDOC 2
#define NQ 16
#define DSEQ 512
#define HDIM 256
#define NHEAD 8
#define HSZ 32
#define NLAYER 2
#define KRBF 128
#define DPOOL 255
#define NSEQ (NB*NDOC)          // 32
#define NROWS (NSEQ*DSEQ)       // 16384
#define NQROWS (NB*NQ)          // 256
#define NBQ (NSEQ*NQ)           // 512
#define NRBFROWS (NBQ*DPOOL)    // 130560

// ------------------------- scratch (static device, no allocs) -------------------
__device__ float g_X[NROWS*HDIM];
__device__ float g_T[NROWS*HDIM];
__device__ float g_FF[NROWS*HDIM];
__device__ float g_QKV[NROWS*3*HDIM];
__device__ float g_O[NROWS*HDIM];
__device__ float g_QE[NQROWS*HDIM];
__device__ float g_QT[NQROWS*HDIM];
__device__ float g_QN[NQROWS*HDIM];
__device__ float g_DN[NROWS*HDIM];
__device__ float g_COS[NBQ*DSEQ];
__device__ float g_YR[(size_t)NRBFROWS*KRBF];
__device__ float g_SVP[2*NRBFROWS];
__device__ float g_SC[NBQ];

// ------------------------- embedding + positional encoding ---------------------
__global__ void embed_doc_kernel(const int* __restrict__ dtok, const float* __restrict__ embw,
                                 float* __restrict__ X) {
  int idx = blockIdx.x*256 + threadIdx.x;
  int h = idx & (HDIM-1);
  int row = idx >> 8;              // bn*512 + t
  int t = row & (DSEQ-1);
  int tok = dtok[row];
  int i = h >> 1;
  float div = expf((float)i * -0.07195578415606394f);
  float ang = (float)t * div;
  float pe = (h & 1) ? cosf(ang) : sinf(ang);
  X[idx] = embw[(size_t)tok*HDIM + h] + pe;
}

__global__ void embed_q_kernel(const int* __restrict__ qtok, const float* __restrict__ embw,
                               float* __restrict__ QE) {
  int idx = blockIdx.x*256 + threadIdx.x;
  int h = idx & (HDIM-1), row = idx >> 8;
  QE[idx] = embw[(size_t)qtok[row]*HDIM + h];
}

// ------------------------- tf32 helpers ----------------------------------------
__device__ __forceinline__ float to_tf32(float x) {
  uint32_t u;
  asm("cvt.rna.tf32.f32 %0, %1;" : "=r"(u) : "f"(x));
  return __uint_as_float(u);
}

__device__ __forceinline__ void mma_tf32(float* c, const float* a, const float* b) {
  asm volatile(
    "mma.sync.aligned.m16n8k8.row.col.f32.tf32.tf32.f32 "
    "{%0,%1,%2,%3}, {%4,%5,%6,%7}, {%8,%9}, {%0,%1,%2,%3};"
    : "+f"(c[0]), "+f"(c[1]), "+f"(c[2]), "+f"(c[3])
    : "r"(__float_as_uint(a[0])), "r"(__float_as_uint(a[1])),
      "r"(__float_as_uint(a[2])), "r"(__float_as_uint(a[3])),
      "r"(__float_as_uint(b[0])), "r"(__float_as_uint(b[1])));
}

__device__ __forceinline__ void cp16(uint32_t s, const void* g) {
  asm volatile("cp.async.cg.shared.global [%0], [%1], 16;\n" :: "r"(s), "l"(g));
}
__device__ __forceinline__ uint32_t saddr(const void* p) {
  return (uint32_t)__cvta_generic_to_shared(p);
}
#define CP_COMMIT() asm volatile("cp.async.commit_group;\n" ::: "memory")
#define CP_WAIT0()  asm volatile("cp.async.wait_group 0;\n" ::: "memory")

// ------------------------- mainloop body (shared by the two GEMM kernels) -------
// As[2][128][20], Bs[2][16][136]; 128x128 block tile, 2x4 warps of 64x32.
// As/Bs are alignas(16): cp.async.cg requires 16B-aligned smem dst.
#define GEMM_LOAD_TILE(st, kt)                                                  \
  do {                                                                          \
    _Pragma("unroll")                                                           \
    for (int it = 0; it < 2; it++) {                                            \
      int slot = tid + it*256;                                                  \
      int r = slot >> 2, c4 = (slot & 3) << 2;                                  \
      cp16(saddr(&As[st][r][c4]), A + (size_t)(rowB + r)*Kd + (kt) + c4);       \
    }                                                                           \
    _Pragma("unroll")                                                           \
    for (int it = 0; it < 2; it++) {                                            \
      int slot = tid + it*256;                                                  \
      int kr = slot >> 5, c4 = (slot & 31) << 2;                                \
      cp16(saddr(&Bs[st][kr][c4]), Bm + (size_t)((kt) + kr)*N + colB + c4);     \
    }                                                                           \
  } while (0)

#define GEMM_COMPUTE_TILE(st)                                                   \
  do {                                                                          \
    _Pragma("unroll")                                                           \
    for (int ks = 0; ks < 2; ks++) {                                            \
      float afr[4][4], bfr[4][2];                                               \
      _Pragma("unroll")                                                         \
      for (int mt = 0; mt < 4; mt++) {                                          \
        int r0 = mBase + mt*16 + gid;                                           \
        afr[mt][0] = As[st][r0    ][ks*8 + tig    ];                            \
        afr[mt][1] = As[st][r0 + 8][ks*8 + tig    ];                            \
        afr[mt][2] = As[st][r0    ][ks*8 + tig + 4];                            \
        afr[mt][3] = As[st][r0 + 8][ks*8 + tig + 4];                            \
      }                                                                         \
      _Pragma("unroll")                                                         \
      for (int nt = 0; nt < 4; nt++) {                                          \
        int n0 = nBase + nt*8 + gid;                                            \
        bfr[nt][0] = Bs[st][ks*8 + tig    ][n0];                                \
        bfr[nt][1] = Bs[st][ks*8 + tig + 4][n0];                                \
      }                                                                         \
      _Pragma("unroll")                                                         \
      for (int mt = 0; mt < 4; mt++)                                            \
        _Pragma("unroll")                                                       \
        for (int nt = 0; nt < 4; nt++)                                          \
          mma_tf32(acc[mt][nt], afr[mt], bfr[nt]);                              \
    }                                                                           \
  } while (0)

#define GEMM_MAINLOOP()                                                         \
  GEMM_LOAD_TILE(0, 0); CP_COMMIT(); CP_WAIT0(); __syncthreads();               \
  {                                                                             \
    int cur = 0;                                                                \
    for (int kt = 0; kt < Kd; kt += 16) {                                       \
      int nxt = kt + 16;                                                        \
      if (nxt < Kd) { GEMM_LOAD_TILE(cur ^ 1, nxt); CP_COMMIT(); }              \
      GEMM_COMPUTE_TILE(cur);                                                   \
      if (nxt < Kd) CP_WAIT0();                                                 \
      __syncthreads();                                                          \
      cur ^= 1;                                                                 \
    }                                                                           \
  }

// ------------------------- tf32 tensor-core GEMM: C = A@B + bias ----------------
template<bool RELU>
__global__ void __launch_bounds__(256)
gemm_tf32_kernel(const float* __restrict__ A, const float* __restrict__ Bm,
                 const float* __restrict__ bias, float* __restrict__ C,
                 int M, int N, int Kd) {
  __shared__ alignas(16) float As[2][128][20];
  __shared__ alignas(16) float Bs[2][16][136];

  const int tid = threadIdx.x;
  const int warp = tid >> 5, lane = tid & 31;
  const int gid = lane >> 2, tig = lane & 3;
  const int warpM = warp >> 2, warpN = warp & 3;
  const int mBase = warpM*64, nBase = warpN*32;
  const int rowB = blockIdx.y*128, colB = blockIdx.x*128;

  float acc[4][4][4];
  #pragma unroll
  for (int i = 0; i < 4; i++)
    #pragma unroll
    for (int j = 0; j < 4; j++)
      #pragma unroll
      for (int k = 0; k < 4; k++) acc[i][j][k] = 0.f;

  GEMM_MAINLOOP();

  #pragma unroll
  for (int mt = 0; mt < 4; mt++) {
    int r0 = rowB + mBase + mt*16 + gid;
    #pragma unroll
    for (int nt = 0; nt < 4; nt++) {
      int c0 = colB + nBase + nt*8 + tig*2;
      float b0 = bias[c0], b1 = bias[c0+1];
      float v0 = acc[mt][nt][0] + b0;
      float v1 = acc[mt][nt][1] + b1;
      float v2 = acc[mt][nt][2] + b0;
      float v3 = acc[mt][nt][3] + b1;
      if (RELU) { v0 = fmaxf(v0,0.f); v1 = fmaxf(v1,0.f); v2 = fmaxf(v2,0.f); v3 = fmaxf(v3,0.f); }
      *(float2*)(C + (size_t)r0*N + c0) = make_float2(v0, v1);
      *(float2*)(C + (size_t)(r0+8)*N + c0) = make_float2(v2, v3);
    }
  }
}

// ------------------------- RBF fc1 GEMM with fused relu + fc2 reduce ------------
// h = relu(Y@W1[:,colB:colB+128] + b1); s_partial = h . w2[colB:colB+128].
// Per-warp 32-col partials are reduced across warpN via smem (no cross-warp
// races), one value per row written to SVp[chunk]. Chunks summed in final_max.
__global__ void __launch_bounds__(256)
gemm_rbf_fused_kernel(const float* __restrict__ A, const float* __restrict__ Bm,
                      const float* __restrict__ bias, const float* __restrict__ w2g,
                      float* __restrict__ SVp) {
  __shared__ alignas(16) float As[2][128][20];
  __shared__ alignas(16) float Bs[2][16][136];
  __shared__ float part[4][128];

  const int N = HDIM, Kd = KRBF;
  const int tid = threadIdx.x;
  const int warp = tid >> 5, lane = tid & 31;
  const int gid = lane >> 2, tig = lane & 3;
  const int warpM = warp >> 2, warpN = warp & 3;
  const int mBase = warpM*64, nBase = warpN*32;
  const int rowB = blockIdx.y*128, colB = blockIdx.x*128;

  float acc[4][4][4];
  #pragma unroll
  for (int i = 0; i < 4; i++)
    #pragma unroll
    for (int j = 0; j < 4; j++)
      #pragma unroll
      for (int k = 0; k < 4; k++) acc[i][j][k] = 0.f;

  GEMM_MAINLOOP();

  float p0[4] = {0.f,0.f,0.f,0.f}, p1[4] = {0.f,0.f,0.f,0.f};
  #pragma unroll
  for (int mt = 0; mt < 4; mt++) {
    #pragma unroll
    for (int nt = 0; nt < 4; nt++) {
      int c0 = colB + nBase + nt*8 + tig*2;
      float b0 = bias[c0], b1 = bias[c0+1];
      float w0 = w2g[c0], w1 = w2g[c0+1];
      float v0 = fmaxf(acc[mt][nt][0] + b0, 0.f);
      float v1 = fmaxf(acc[mt][nt][1] + b1, 0.f);
      float v2 = fmaxf(acc[mt][nt][2] + b0, 0.f);
      float v3 = fmaxf(acc[mt][nt][3] + b1, 0.f);
      p0[mt] += v0*w0 + v1*w1;
      p1[mt] += v2*w0 + v3*w1;
    }
  }
  // sum the 4 tig lanes of each quad -> full 32-col partial for this warp
  #pragma unroll
  for (int mt = 0; mt < 4; mt++) {
    #pragma unroll
    for (int off = 1; off <= 2; off <<= 1) {
      p0[mt] += __shfl_xor_sync(0xffffffffu, p0[mt], off);
      p1[mt] += __shfl_xor_sync(0xffffffffu, p1[mt], off);
    }
    if (tig == 0) {
      int lr = mBase + mt*16 + gid;          // local row 0..127 (warpM splits rows)
      part[warpN][lr]     = p0[mt];
      part[warpN][lr + 8] = p1[mt];
    }
  }
  __syncthreads();
  // sum across the 4 warpN column-groups
  if (tid < 128) {
    float s = part[0][tid] + part[1][tid] + part[2][tid] + part[3][tid];
    SVp[(size_t)blockIdx.x*NRBFROWS + rowB + tid] = s;
  }
}

// ------------------------- fused flash attention --------------------------------
__global__ void __launch_bounds__(128)
attn_fused_kernel(const float* __restrict__ QKV, const float* __restrict__ mask_d,
                  float* __restrict__ O) {
  __shared__ float Ks[64][36];
  __shared__ float Vt[32][36];
  __shared__ float Ps[4][16][68];
  __shared__ float ms[64];

  const int bnh = blockIdx.y, bn = bnh >> 3, h = bnh & 7;
  const int q0 = blockIdx.x*64;
  const int tid = threadIdx.x;
  const int warp = tid >> 5, lane = tid & 31;
  const int gid = lane >> 2, tig = lane & 3;
  const float scale = 0.17677669529663687f;

  const float* Qp = QKV + (size_t)bn*DSEQ*768 + h*HSZ;
  const float* Kp = Qp + HDIM;
  const float* Vp = Qp + 2*HDIM;
  const float* mp = mask_d + bn*DSEQ;

  float (*Qs)[36] = (float(*)[36])&Ps[0][0][0];
  #pragma unroll
  for (int i = 0; i < 4; i++) {
    int slot = tid + i*128;
    int r = slot >> 3, c4 = (slot & 7) << 2;
    float4 v = *(const float4*)(Qp + (size_t)(q0 + r)*768 + c4);
    v.x = to_tf32(v.x); v.y = to_tf32(v.y); v.z = to_tf32(v.z); v.w = to_tf32(v.w);
    *(float4*)&Qs[r][c4] = v;
  }
  __syncthreads();
  float aq[4][4];
  #pragma unroll
  for (int ks = 0; ks < 4; ks++) {
    int r0 = warp*16 + gid;
    aq[ks][0] = Qs[r0    ][ks*8 + tig    ];
    aq[ks][1] = Qs[r0 + 8][ks*8 + tig    ];
    aq[ks][2] = Qs[r0    ][ks*8 + tig + 4];
    aq[ks][3] = Qs[r0 + 8][ks*8 + tig + 4];
  }

  float oacc[4][4] = {};
  float m0 = -1e30f, m1 = -1e30f, l0 = 0.f, l1 = 0.f;

  for (int kc = 0; kc < DSEQ; kc += 64) {
    if (mp[kc] == 0.f) continue;
    __syncthreads();

    #pragma unroll
    for (int i = 0; i < 4; i++) {
      int slot = tid + i*128;
      int r = slot >> 3, c4 = (slot & 7) << 2;
      float4 kv = *(const float4*)(Kp + (size_t)(kc + r)*768 + c4);
      kv.x = to_tf32(kv.x); kv.y = to_tf32(kv.y); kv.z = to_tf32(kv.z); kv.w = to_tf32(kv.w);
      *(float4*)&Ks[r][c4] = kv;
      float4 vv = *(const float4*)(Vp + (size_t)(kc + r)*768 + c4);
      Vt[c4+0][r] = to_tf32(vv.x); Vt[c4+1][r] = to_tf32(vv.y);
      Vt[c4+2][r] = to_tf32(vv.z); Vt[c4+3][r] = to_tf32(vv.w);
    }
    if (tid < 64) ms[tid] = mp[kc + tid];
    __syncthreads();

    float sacc[8][4];
    #pragma unroll
    for (int nt = 0; nt < 8; nt++)
      #pragma unroll
      for (int k = 0; k < 4; k++) sacc[nt][k] = 0.f;
    #pragma unroll
    for (int ks = 0; ks < 4; ks++) {
      #pragma unroll
      for (int nt = 0; nt < 8; nt++) {
        float b[2];
        b[0] = Ks[nt*8 + gid][ks*8 + tig    ];
        b[1] = Ks[nt*8 + gid][ks*8 + tig + 4];
        mma_tf32(sacc[nt], aq[ks], b);
      }
    }

    float mr0 = -1e30f, mr1 = -1e30f;
    #pragma unroll
    for (int nt = 0; nt < 8; nt++) {
      int j0 = nt*8 + tig*2;
      bool v0 = ms[j0] > 0.f, v1 = ms[j0+1] > 0.f;
      sacc[nt][0] = v0 ? sacc[nt][0]*scale : -1e9f;
      sacc[nt][1] = v1 ? sacc[nt][1]*scale : -1e9f;
      sacc[nt][2] = v0 ? sacc[nt][2]*scale : -1e9f;
      sacc[nt][3] = v1 ? sacc[nt][3]*scale : -1e9f;
      mr0 = fmaxf(mr0, fmaxf(sacc[nt][0], sacc[nt][1]));
      mr1 = fmaxf(mr1, fmaxf(sacc[nt][2], sacc[nt][3]));
    }
    #pragma unroll
    for (int off = 1; off <= 2; off <<= 1) {
      mr0 = fmaxf(mr0, __shfl_xor_sync(0xffffffffu, mr0, off));
      mr1 = fmaxf(mr1, __shfl_xor_sync(0xffffffffu, mr1, off));
    }
    float nm0 = fmaxf(m0, mr0), nm1 = fmaxf(m1, mr1);
    float al0 = __expf(m0 - nm0), al1 = __expf(m1 - nm1);
    m0 = nm0; m1 = nm1;

    float sum0 = 0.f, sum1 = 0.f;
    #pragma unroll
    for (int nt = 0; nt < 8; nt++) {
      float p0 = __expf(sacc[nt][0] - nm0);
      float p1 = __expf(sacc[nt][1] - nm0);
      float p2 = __expf(sacc[nt][2] - nm1);
      float p3 = __expf(sacc[nt][3] - nm1);
      sum0 += p0 + p1; sum1 += p2 + p3;
      int j0 = nt*8 + tig*2;
      Ps[warp][gid    ][j0] = to_tf32(p0); Ps[warp][gid    ][j0+1] = to_tf32(p1);
      Ps[warp][gid + 8][j0] = to_tf32(p2); Ps[warp][gid + 8][j0+1] = to_tf32(p3);
    }
    #pragma unroll
    for (int off = 1; off <= 2; off <<= 1) {
      sum0 += __shfl_xor_sync(0xffffffffu, sum0, off);
      sum1 += __shfl_xor_sync(0xffffffffu, sum1, off);
    }
    l0 = l0*al0 + sum0;
    l1 = l1*al1 + sum1;

    #pragma unroll
    for (int nt = 0; nt < 4; nt++) {
      oacc[nt][0] *= al0; oacc[nt][1] *= al0;
      oacc[nt][2] *= al1; oacc[nt][3] *= al1;
    }
    __syncwarp();

    #pragma unroll
    for (int kt = 0; kt < 8; kt++) {
      float ap[4];
      ap[0] = Ps[warp][gid    ][kt*8 + tig    ];
      ap[1] = Ps[warp][gid + 8][kt*8 + tig    ];
      ap[2] = Ps[warp][gid    ][kt*8 + tig + 4];
      ap[3] = Ps[warp][gid + 8][kt*8 + tig + 4];
      #pragma unroll
      for (int nt = 0; nt < 4; nt++) {
        float b[2];
        b[0] = Vt[nt*8 + gid][kt*8 + tig    ];
        b[1] = Vt[nt*8 + gid][kt*8 + tig + 4];
        mma_tf32(oacc[nt], ap, b);
      }
    }
  }

  float inv0 = 1.f / l0, inv1 = 1.f / l1;
  int rg0 = bn*DSEQ + q0 + warp*16 + gid;
  #pragma unroll
  for (int nt = 0; nt < 4; nt++) {
    int c0 = h*HSZ + nt*8 + tig*2;
    *(float2*)(O + (size_t)rg0*HDIM + c0)     = make_float2(oacc[nt][0]*inv0, oacc[nt][1]*inv0);
    *(float2*)(O + (size_t)(rg0+8)*HDIM + c0) = make_float2(oacc[nt][2]*inv1, oacc[nt][3]*inv1);
  }
}

// ------------------------- residual + LayerNorm --------------------------------
__global__ void add_ln_kernel(const float* __restrict__ Xin, const float* __restrict__ Y,
                              const float* __restrict__ g, const float* __restrict__ b,
                              float* __restrict__ Out) {
  __shared__ float red[256];
  int row = blockIdx.x, tid = threadIdx.x;
  float v = Xin[(size_t)row*HDIM + tid] + Y[(size_t)row*HDIM + tid];
  red[tid] = v; __syncthreads();
  for (int s = 128; s > 0; s >>= 1) { if (tid < s) red[tid] += red[tid+s]; __syncthreads(); }
  float mean = red[0] * (1.f/HDIM);
  __syncthreads();
  float dv = v - mean;
  red[tid] = dv*dv; __syncthreads();
  for (int s = 128; s > 0; s >>= 1) { if (tid < s) red[tid] += red[tid+s]; __syncthreads(); }
  float var = red[0] * (1.f/HDIM);
  Out[(size_t)row*HDIM + tid] = dv * rsqrtf(var + 1e-5f) * g[tid] + b[tid];
}

// ------------------------- cosine head ------------------------------------------
__global__ void rownorm_kernel(const float* __restrict__ In, float* __restrict__ Out) {
  __shared__ float red[256];
  int row = blockIdx.x, tid = threadIdx.x;
  float v = In[(size_t)row*HDIM + tid];
  red[tid] = v*v; __syncthreads();
  for (int s=128; s>0; s>>=1){ if(tid<s) red[tid]+=red[tid+s]; __syncthreads(); }
  float n = fmaxf(sqrtf(red[0]), 1e-8f);
  Out[(size_t)row*HDIM + tid] = v / n;
}

__global__ void dc_norm_kernel(const int* __restrict__ dtok, const float* __restrict__ embw,
                               const float* __restrict__ Xf, const float* __restrict__ wc,
                               const float* __restrict__ bc, float* __restrict__ DN) {
  __shared__ float red[256];
  int row = blockIdx.x, tid = threadIdx.x;
  float de = embw[(size_t)dtok[row]*HDIM + tid];
  float v = wc[0]*de + wc[1]*Xf[(size_t)row*HDIM + tid] + bc[0];
  red[tid] = v*v; __syncthreads();
  for (int s=128;s>0;s>>=1){ if(tid<s) red[tid]+=red[tid+s]; __syncthreads(); }
  float n = fmaxf(sqrtf(red[0]), 1e-8f);
  DN[(size_t)row*HDIM + tid] = v / n;
}

__global__ void cos_kernel(const float* __restrict__ QN, const float* __restrict__ DN,
                           float* __restrict__ COS) {
  __shared__ float Qs[NQ*HDIM];
  int bn = blockIdx.y;
  int b = bn >> 1;
  int t = blockIdx.x*128 + threadIdx.x;
  for (int i = threadIdx.x; i < NQ*HDIM; i += 128) Qs[i] = QN[(size_t)b*NQ*HDIM + i];
  __syncthreads();
  const float* dp = DN + ((size_t)bn*DSEQ + t)*HDIM;
  float acc[NQ] = {};
  for (int hh = 0; hh < HDIM; hh++) {
    float dv = dp[hh];
    #pragma unroll
    for (int qq = 0; qq < NQ; qq++) acc[qq] = fmaf(dv, Qs[qq*HDIM+hh], acc[qq]);
  }
  #pragma unroll
  for (int qq = 0; qq < NQ; qq++)
    COS[((size_t)bn*NQ + qq)*DSEQ + t] = acc[qq];
}

// ------------------------- RBF pooling ------------------------------------------
__global__ void rbf_y_kernel(const float* __restrict__ COS, const float* __restrict__ mask_d,
                             float* __restrict__ Y) {
  size_t idx = (size_t)blockIdx.x*256 + threadIdx.x;
  int k = (int)(idx & (KRBF-1));
  int row = (int)(idx >> 7);
  int dp = row % DPOOL;
  int bq = row / DPOOL;
  int bn = bq >> 4;
  const float* cr = COS + (size_t)bq*DSEQ + dp*2;
  const float* mr = mask_d + bn*DSEQ + dp*2;
  float mu = 1.f - (float)k*(2.f/KRBF);
  float s = 0.f;
  #pragma unroll
  for (int j = 0; j < 4; j++) {
    float c = cr[j] - mu;
    s += mr[j]*__expf(-50.f*c*c);
  }
  Y[idx] = __logf(s + 1e-6f);
}

__global__ void final_max_kernel(const float* __restrict__ SVp, const float* __restrict__ b2,
                                 float* __restrict__ SC) {
  __shared__ float red[256];
  int bq = blockIdx.x, tid = threadIdx.x;
  float mx = -1e30f;
  if (tid < DPOOL) {
    size_t r = (size_t)bq*DPOOL + tid;
    mx = SVp[r] + SVp[NRBFROWS + r];
  }
  red[tid] = mx; __syncthreads();
  for (int s=128;s>0;s>>=1){ if(tid<s) red[tid]=fmaxf(red[tid],red[tid+s]); __syncthreads(); }
  if (tid==0) SC[bq] = red[0] + b2[0];
}

__global__ void final_sum_kernel(const float* __restrict__ SC, const float* __restrict__ mask_q,
                                 float* __restrict__ out) {
  int bn = threadIdx.x;       // 32
  int b = bn >> 1;
  float s = 0.f;
  #pragma unroll
  for (int qq = 0; qq < NQ; qq++)
    s += SC[bn*NQ + qq] * mask_q[b*NQ + qq];
  out[bn] = s;
}

// ------------------------- launcher ---------------------------------------------
extern "C" void kernel_launch(void* const* d_in, const int* in_sizes, int n_in,
                              void* d_out, int out_size) {
  const int*   qtok     = (const int*)d_in[0];
  const int*   dtok     = (const int*)d_in[1];
  const float* mask_q   = (const float*)d_in[2];
  const float* mask_d   = (const float*)d_in[3];
  const float* embw     = (const float*)d_in[4];
  const float* fc_qt_w  = (const float*)d_in[5];
  const float* fc_qt_b  = (const float*)d_in[6];
  const float* qkv_w    = (const float*)d_in[7];
  const float* qkv_b    = (const float*)d_in[8];
  const float* out_w    = (const float*)d_in[9];
  const float* out_b    = (const float*)d_in[10];
  const float* ln1_g    = (const float*)d_in[11];
  const float* ln1_b    = (const float*)d_in[12];
  const float* w1       = (const float*)d_in[13];
  const float* b1       = (const float*)d_in[14];
  const float* w2       = (const float*)d_in[15];
  const float* b2       = (const float*)d_in[16];
  const float* ln2_g    = (const float*)d_in[17];
  const float* ln2_b    = (const float*)d_in[18];
  const float* fc_ctx_w = (const float*)d_in[19];
  const float* fc_ctx_b = (const float*)d_in[20];
  const float* rb1w     = (const float*)d_in[21];
  const float* rb1b     = (const float*)d_in[22];
  const float* rb2w     = (const float*)d_in[23];
  const float* rb2b     = (const float*)d_in[24];
  float* out = (float*)d_out;

  void* p;
  cudaGetSymbolAddress(&p, g_X);   float* X   = (float*)p;
  cudaGetSymbolAddress(&p, g_T);   float* T   = (float*)p;
  cudaGetSymbolAddress(&p, g_FF);  float* FF  = (float*)p;
  cudaGetSymbolAddress(&p, g_QKV); float* QKV = (float*)p;
  cudaGetSymbolAddress(&p, g_O);   float* O   = (float*)p;
  cudaGetSymbolAddress(&p, g_QE);  float* QE  = (float*)p;
  cudaGetSymbolAddress(&p, g_QT);  float* QT  = (float*)p;
  cudaGetSymbolAddress(&p, g_QN);  float* QN  = (float*)p;
  cudaGetSymbolAddress(&p, g_DN);  float* DN  = (float*)p;
  cudaGetSymbolAddress(&p, g_COS); float* COS = (float*)p;
  cudaGetSymbolAddress(&p, g_YR);  float* YR  = (float*)p;
  cudaGetSymbolAddress(&p, g_SVP); float* SVp = (float*)p;
  cudaGetSymbolAddress(&p, g_SC);  float* SC  = (float*)p;

  embed_doc_kernel<<<NROWS*HDIM/256, 256>>>(dtok, embw, X);

  for (int l = 0; l < NLAYER; l++) {
    gemm_tf32_kernel<false><<<dim3(768/128, NROWS/128), 256>>>(
        X, qkv_w + (size_t)l*HDIM*768, qkv_b + l*768, QKV, NROWS, 768, HDIM);
    attn_fused_kernel<<<dim3(DSEQ/64, NSEQ*NHEAD), 128>>>(QKV, mask_d, O);
    gemm_tf32_kernel<false><<<dim3(2, NROWS/128), 256>>>(
        O, out_w + (size_t)l*HDIM*HDIM, out_b + l*HDIM, T, NROWS, HDIM, HDIM);
    add_ln_kernel<<<NROWS,256>>>(X, T, ln1_g+l*HDIM, ln1_b+l*HDIM, X);
    gemm_tf32_kernel<true><<<dim3(2, NROWS/128), 256>>>(
        X, w1 + (size_t)l*HDIM*HDIM, b1 + l*HDIM, FF, NROWS, HDIM, HDIM);
    gemm_tf32_kernel<false><<<dim3(2, NROWS/128), 256>>>(
        FF, w2 + (size_t)l*HDIM*HDIM, b2 + l*HDIM, T, NROWS, HDIM, HDIM);
    add_ln_kernel<<<NROWS,256>>>(X, T, ln2_g+l*HDIM, ln2_b+l*HDIM, X);
  }

  embed_q_kernel<<<NQROWS*HDIM/256,256>>>(qtok, embw, QE);
  gemm_tf32_kernel<false><<<dim3(2, NQROWS/128), 256>>>(QE, fc_qt_w, fc_qt_b, QT, NQROWS, HDIM, HDIM);
  rownorm_kernel<<<NQROWS,256>>>(QT, QN);
  dc_norm_kernel<<<NROWS,256>>>(dtok, embw, X, fc_ctx_w, fc_ctx_b, DN);
  cos_kernel<<<dim3(DSEQ/128, NSEQ),128>>>(QN, DN, COS);

  rbf_y_kernel<<<NRBFROWS*KRBF/256, 256>>>(COS, mask_d, YR);
  gemm_rbf_fused_kernel<<<dim3(2, NRBFROWS/128), 256>>>(YR, rb1w, rb1b, rb2w, SVp);
  final_max_kernel<<<NBQ,256>>>(SVp, rb2b, SC);
  final_sum_kernel<<<1,32>>>(SC, mask_q, out);
}

// round 8
// speedup vs baseline: 2.8755x; 1.0037x over previous
#include <cuda_runtime.h>
#include <math.h>
#include <stdint.h>

#define NB 16
#define NDOC 2
#define NQ 16
#define DSEQ 512
#define HDIM 256
#define NHEAD 8
#define HSZ 32
#define NLAYER 2
#define KRBF 128
#define DPOOL 255
#define NSEQ (NB*NDOC)          // 32
#define NROWS (NSEQ*DSEQ)       // 16384
#define NQROWS (NB*NQ)          // 256
#define NBQ (NSEQ*NQ)           // 512
#define NRBFROWS (NBQ*DPOOL)    // 130560

// ------------------------- scratch (static device, no allocs) -------------------
__device__ float g_X[NROWS*HDIM];
__device__ float g_T[NROWS*HDIM];
__device__ float g_FF[NROWS*HDIM];
__device__ float g_QKV[NROWS*3*HDIM];
__device__ float g_O[NROWS*HDIM];
__device__ float g_QE[NQROWS*HDIM];
__device__ float g_QT[NQROWS*HDIM];
__device__ float g_QN[NQROWS*HDIM];
__device__ float g_DN[NROWS*HDIM];
__device__ float g_COS[NBQ*DSEQ];
__device__ float g_YR[(size_t)NRBFROWS*KRBF];
__device__ float g_SVP[2*NRBFROWS];
__device__ float g_SC[NBQ];

// ------------------------- embedding + positional encoding ---------------------
__global__ void embed_doc_kernel(const int* __restrict__ dtok, const float* __restrict__ embw,
                                 float* __restrict__ X) {
  int idx = blockIdx.x*256 + threadIdx.x;
  int h = idx & (HDIM-1);
  int row = idx >> 8;              // bn*512 + t
  int t = row & (DSEQ-1);
  int tok = dtok[row];
  int i = h >> 1;
  float div = expf((float)i * -0.07195578415606394f);
  float ang = (float)t * div;
  float pe = (h & 1) ? cosf(ang) : sinf(ang);
  X[idx] = embw[(size_t)tok*HDIM + h] + pe;
}

__global__ void embed_q_kernel(const int* __restrict__ qtok, const float* __restrict__ embw,
                               float* __restrict__ QE) {
  int idx = blockIdx.x*256 + threadIdx.x;
  int h = idx & (HDIM-1), row = idx >> 8;
  QE[idx] = embw[(size_t)qtok[row]*HDIM + h];
}

// ------------------------- tf32 helpers ----------------------------------------
__device__ __forceinline__ float to_tf32(float x) {
  uint32_t u;
  asm("cvt.rna.tf32.f32 %0, %1;" : "=r"(u) : "f"(x));
  return __uint_as_float(u);
}

__device__ __forceinline__ void mma_tf32(float* c, const float* a, const float* b) {
  asm volatile(
    "mma.sync.aligned.m16n8k8.row.col.f32.tf32.tf32.f32 "
    "{%0,%1,%2,%3}, {%4,%5,%6,%7}, {%8,%9}, {%0,%1,%2,%3};"
    : "+f"(c[0]), "+f"(c[1]), "+f"(c[2]), "+f"(c[3])
    : "r"(__float_as_uint(a[0])), "r"(__float_as_uint(a[1])),
      "r"(__float_as_uint(a[2])), "r"(__float_as_uint(a[3])),
      "r"(__float_as_uint(b[0])), "r"(__float_as_uint(b[1])));
}

__device__ __forceinline__ void cp16(uint32_t s, const void* g) {
  asm volatile("cp.async.cg.shared.global [%0], [%1], 16;\n" :: "r"(s), "l"(g));
}
__device__ __forceinline__ uint32_t saddr(const void* p) {
  return (uint32_t)__cvta_generic_to_shared(p);
}
#define CP_COMMIT() asm volatile("cp.async.commit_group;\n" ::: "memory")
#define CP_WAIT0()  asm volatile("cp.async.wait_group 0;\n" ::: "memory")

// ------------------------- mainloop body (shared by the two GEMM kernels) -------
// As[2][128][20], Bs[2][16][136]; 128x128 block tile, 2x4 warps of 64x32.
// As/Bs are alignas(16): cp.async.cg requires 16B-aligned smem dst.
#define GEMM_LOAD_TILE(st, kt)                                                  \
  do {                                                                          \
    _Pragma("unroll")                                                           \
    for (int it = 0; it < 2; it++) {                                            \
      int slot = tid + it*256;                                                  \
      int r = slot >> 2, c4 = (slot & 3) << 2;                                  \
      cp16(saddr(&As[st][r][c4]), A + (size_t)(rowB + r)*Kd + (kt) + c4);       \
    }                                                                           \
    _Pragma("unroll")                                                           \
    for (int it = 0; it < 2; it++) {                                            \
      int slot = tid + it*256;                                                  \
      int kr = slot >> 5, c4 = (slot & 31) << 2;                                \
      cp16(saddr(&Bs[st][kr][c4]), Bm + (size_t)((kt) + kr)*N + colB + c4);     \
    }                                                                           \
  } while (0)

#define GEMM_COMPUTE_TILE(st)                                                   \
  do {                                                                          \
    _Pragma("unroll")                                                           \
    for (int ks = 0; ks < 2; ks++) {                                            \
      float afr[4][4], bfr[4][2];                                               \
      _Pragma("unroll")                                                         \
      for (int mt = 0; mt < 4; mt++) {                                          \
        int r0 = mBase + mt*16 + gid;                                           \
        afr[mt][0] = As[st][r0    ][ks*8 + tig    ];                            \
        afr[mt][1] = As[st][r0 + 8][ks*8 + tig    ];                            \
        afr[mt][2] = As[st][r0    ][ks*8 + tig + 4];                            \
        afr[mt][3] = As[st][r0 + 8][ks*8 + tig + 4];                            \
      }                                                                         \
      _Pragma("unroll")                                                         \
      for (int nt = 0; nt < 4; nt++) {                                          \
        int n0 = nBase + nt*8 + gid;                                            \
        bfr[nt][0] = Bs[st][ks*8 + tig    ][n0];                                \
        bfr[nt][1] = Bs[st][ks*8 + tig + 4][n0];                                \
      }                                                                         \
      _Pragma("unroll")                                                         \
      for (int mt = 0; mt < 4; mt++)                                            \
        _Pragma("unroll")                                                       \
        for (int nt = 0; nt < 4; nt++)                                          \
          mma_tf32(acc[mt][nt], afr[mt], bfr[nt]);                              \
    }                                                                           \
  } while (0)

#define GEMM_MAINLOOP()                                                         \
  GEMM_LOAD_TILE(0, 0); CP_COMMIT(); CP_WAIT0(); __syncthreads();               \
  {                                                                             \
    int cur = 0;                                                                \
    for (int kt = 0; kt < Kd; kt += 16) {                                       \
      int nxt = kt + 16;                                                        \
      if (nxt < Kd) { GEMM_LOAD_TILE(cur ^ 1, nxt); CP_COMMIT(); }              \
      GEMM_COMPUTE_TILE(cur);                                                   \
      if (nxt < Kd) CP_WAIT0();                                                 \
      __syncthreads();                                                          \
      cur ^= 1;                                                                 \
    }                                                                           \
  }

// ------------------------- tf32 tensor-core GEMM: C = A@B + bias ----------------
template<bool RELU>
__global__ void __launch_bounds__(256)
gemm_tf32_kernel(const float* __restrict__ A, const float* __restrict__ Bm,
                 const float* __restrict__ bias, float* __restrict__ C,
                 int M, int N, int Kd) {
  __shared__ alignas(16) float As[2][128][20];
  __shared__ alignas(16) float Bs[2][16][136];

  const int tid = threadIdx.x;
  const int warp = tid >> 5, lane = tid & 31;
  const int gid = lane >> 2, tig = lane & 3;
  const int warpM = warp >> 2, warpN = warp & 3;
  const int mBase = warpM*64, nBase = warpN*32;
  const int rowB = blockIdx.y*128, colB = blockIdx.x*128;

  float acc[4][4][4];
  #pragma unroll
  for (int i = 0; i < 4; i++)
    #pragma unroll
    for (int j = 0; j < 4; j++)
      #pragma unroll
      for (int k = 0; k < 4; k++) acc[i][j][k] = 0.f;

  GEMM_MAINLOOP();

  #pragma unroll
  for (int mt = 0; mt < 4; mt++) {
    int r0 = rowB + mBase + mt*16 + gid;
    #pragma unroll
    for (int nt = 0; nt < 4; nt++) {
      int c0 = colB + nBase + nt*8 + tig*2;
      float b0 = bias[c0], b1 = bias[c0+1];
      float v0 = acc[mt][nt][0] + b0;
      float v1 = acc[mt][nt][1] + b1;
      float v2 = acc[mt][nt][2] + b0;
      float v3 = acc[mt][nt][3] + b1;
      if (RELU) { v0 = fmaxf(v0,0.f); v1 = fmaxf(v1,0.f); v2 = fmaxf(v2,0.f); v3 = fmaxf(v3,0.f); }
      *(float2*)(C + (size_t)r0*N + c0) = make_float2(v0, v1);
      *(float2*)(C + (size_t)(r0+8)*N + c0) = make_float2(v2, v3);
    }
  }
}

// ------------------------- RBF fc1 GEMM with fused relu + fc2 reduce ------------
// h = relu(Y@W1[:,colB:colB+128] + b1); s_partial = h . w2[colB:colB+128].
// Per-warp 32-col partials are reduced across warpN via smem (no cross-warp
// races), one value per row written to SVp[chunk]. Chunks summed in final_max.
__global__ void __launch_bounds__(256)
gemm_rbf_fused_kernel(const float* __restrict__ A, const float* __restrict__ Bm,
                      const float* __restrict__ bias, const float* __restrict__ w2g,
                      float* __restrict__ SVp) {
  __shared__ alignas(16) float As[2][128][20];
  __shared__ alignas(16) float Bs[2][16][136];
  __shared__ float part[4][128];

  const int N = HDIM, Kd = KRBF;
  const int tid = threadIdx.x;
  const int warp = tid >> 5, lane = tid & 31;
  const int gid = lane >> 2, tig = lane & 3;
  const int warpM = warp >> 2, warpN = warp & 3;
  const int mBase = warpM*64, nBase = warpN*32;
  const int rowB = blockIdx.y*128, colB = blockIdx.x*128;

  float acc[4][4][4];
  #pragma unroll
  for (int i = 0; i < 4; i++)
    #pragma unroll
    for (int j = 0; j < 4; j++)
      #pragma unroll
      for (int k = 0; k < 4; k++) acc[i][j][k] = 0.f;

  GEMM_MAINLOOP();

  float p0[4] = {0.f,0.f,0.f,0.f}, p1[4] = {0.f,0.f,0.f,0.f};
  #pragma unroll
  for (int mt = 0; mt < 4; mt++) {
    #pragma unroll
    for (int nt = 0; nt < 4; nt++) {
      int c0 = colB + nBase + nt*8 + tig*2;
      float b0 = bias[c0], b1 = bias[c0+1];
      float w0 = w2g[c0], w1 = w2g[c0+1];
      float v0 = fmaxf(acc[mt][nt][0] + b0, 0.f);
      float v1 = fmaxf(acc[mt][nt][1] + b1, 0.f);
      float v2 = fmaxf(acc[mt][nt][2] + b0, 0.f);
      float v3 = fmaxf(acc[mt][nt][3] + b1, 0.f);
      p0[mt] += v0*w0 + v1*w1;
      p1[mt] += v2*w0 + v3*w1;
    }
  }
  // sum the 4 tig lanes of each quad -> full 32-col partial for this warp
  #pragma unroll
  for (int mt = 0; mt < 4; mt++) {
    #pragma unroll
    for (int off = 1; off <= 2; off <<= 1) {
      p0[mt] += __shfl_xor_sync(0xffffffffu, p0[mt], off);
      p1[mt] += __shfl_xor_sync(0xffffffffu, p1[mt], off);
    }
    if (tig == 0) {
      int lr = mBase + mt*16 + gid;          // local row 0..127 (warpM splits rows)
      part[warpN][lr]     = p0[mt];
      part[warpN][lr + 8] = p1[mt];
    }
  }
  __syncthreads();
  // sum across the 4 warpN column-groups
  if (tid < 128) {
    float s = part[0][tid] + part[1][tid] + part[2][tid] + part[3][tid];
    SVp[(size_t)blockIdx.x*NRBFROWS + rowB + tid] = s;
  }
}

// ------------------------- fused flash attention --------------------------------
__global__ void __launch_bounds__(128)
attn_fused_kernel(const float* __restrict__ QKV, const float* __restrict__ mask_d,
                  float* __restrict__ O) {
  __shared__ float Ks[64][36];
  __shared__ float Vt[32][36];
  __shared__ float Ps[4][16][68];
  __shared__ float ms[64];

  const int bnh = blockIdx.y, bn = bnh >> 3, h = bnh & 7;
  const int q0 = blockIdx.x*64;
  const int tid = threadIdx.x;
  const int warp = tid >> 5, lane = tid & 31;
  const int gid = lane >> 2, tig = lane & 3;
  const float scale = 0.17677669529663687f;

  const float* Qp = QKV + (size_t)bn*DSEQ*768 + h*HSZ;
  const float* Kp = Qp + HDIM;
  const float* Vp = Qp + 2*HDIM;
  const float* mp = mask_d + bn*DSEQ;

  float (*Qs)[36] = (float(*)[36])&Ps[0][0][0];
  #pragma unroll
  for (int i = 0; i < 4; i++) {
    int slot = tid + i*128;
    int r = slot >> 3, c4 = (slot & 7) << 2;
    float4 v = *(const float4*)(Qp + (size_t)(q0 + r)*768 + c4);
    v.x = to_tf32(v.x); v.y = to_tf32(v.y); v.z = to_tf32(v.z); v.w = to_tf32(v.w);
    *(float4*)&Qs[r][c4] = v;
  }
  __syncthreads();
  float aq[4][4];
  #pragma unroll
  for (int ks = 0; ks < 4; ks++) {
    int r0 = warp*16 + gid;
    aq[ks][0] = Qs[r0    ][ks*8 + tig    ];
    aq[ks][1] = Qs[r0 + 8][ks*8 + tig    ];
    aq[ks][2] = Qs[r0    ][ks*8 + tig + 4];
    aq[ks][3] = Qs[r0 + 8][ks*8 + tig + 4];
  }

  float oacc[4][4] = {};
  float m0 = -1e30f, m1 = -1e30f, l0 = 0.f, l1 = 0.f;

  for (int kc = 0; kc < DSEQ; kc += 64) {
    if (mp[kc] == 0.f) continue;
    __syncthreads();

    #pragma unroll
    for (int i = 0; i < 4; i++) {
      int slot = tid + i*128;
      int r = slot >> 3, c4 = (slot & 7) << 2;
      float4 kv = *(const float4*)(Kp + (size_t)(kc + r)*768 + c4);
      kv.x = to_tf32(kv.x); kv.y = to_tf32(kv.y); kv.z = to_tf32(kv.z); kv.w = to_tf32(kv.w);
      *(float4*)&Ks[r][c4] = kv;
      float4 vv = *(const float4*)(Vp + (size_t)(kc + r)*768 + c4);
      Vt[c4+0][r] = to_tf32(vv.x); Vt[c4+1][r] = to_tf32(vv.y);
      Vt[c4+2][r] = to_tf32(vv.z); Vt[c4+3][r] = to_tf32(vv.w);
    }
    if (tid < 64) ms[tid] = mp[kc + tid];
    __syncthreads();

    float sacc[8][4];
    #pragma unroll
    for (int nt = 0; nt < 8; nt++)
      #pragma unroll
      for (int k = 0; k < 4; k++) sacc[nt][k] = 0.f;
    #pragma unroll
    for (int ks = 0; ks < 4; ks++) {
      #pragma unroll
      for (int nt = 0; nt < 8; nt++) {
        float b[2];
        b[0] = Ks[nt*8 + gid][ks*8 + tig    ];
        b[1] = Ks[nt*8 + gid][ks*8 + tig + 4];
        mma_tf32(sacc[nt], aq[ks], b);
      }
    }

    float mr0 = -1e30f, mr1 = -1e30f;
    #pragma unroll
    for (int nt = 0; nt < 8; nt++) {
      int j0 = nt*8 + tig*2;
      bool v0 = ms[j0] > 0.f, v1 = ms[j0+1] > 0.f;
      sacc[nt][0] = v0 ? sacc[nt][0]*scale : -1e9f;
      sacc[nt][1] = v1 ? sacc[nt][1]*scale : -1e9f;
      sacc[nt][2] = v0 ? sacc[nt][2]*scale : -1e9f;
      sacc[nt][3] = v1 ? sacc[nt][3]*scale : -1e9f;
      mr0 = fmaxf(mr0, fmaxf(sacc[nt][0], sacc[nt][1]));
      mr1 = fmaxf(mr1, fmaxf(sacc[nt][2], sacc[nt][3]));
    }
    #pragma unroll
    for (int off = 1; off <= 2; off <<= 1) {
      mr0 = fmaxf(mr0, __shfl_xor_sync(0xffffffffu, mr0, off));
      mr1 = fmaxf(mr1, __shfl_xor_sync(0xffffffffu, mr1, off));
    }
    float nm0 = fmaxf(m0, mr0), nm1 = fmaxf(m1, mr1);
    float al0 = __expf(m0 - nm0), al1 = __expf(m1 - nm1);
    m0 = nm0; m1 = nm1;

    float sum0 = 0.f, sum1 = 0.f;
    #pragma unroll
    for (int nt = 0; nt < 8; nt++) {
      float p0 = __expf(sacc[nt][0] - nm0);
      float p1 = __expf(sacc[nt][1] - nm0);
      float p2 = __expf(sacc[nt][2] - nm1);
      float p3 = __expf(sacc[nt][3] - nm1);
      sum0 += p0 + p1; sum1 += p2 + p3;
      int j0 = nt*8 + tig*2;
      Ps[warp][gid    ][j0] = to_tf32(p0); Ps[warp][gid    ][j0+1] = to_tf32(p1);
      Ps[warp][gid + 8][j0] = to_tf32(p2); Ps[warp][gid + 8][j0+1] = to_tf32(p3);
    }
    #pragma unroll
    for (int off = 1; off <= 2; off <<= 1) {
      sum0 += __shfl_xor_sync(0xffffffffu, sum0, off);
      sum1 += __shfl_xor_sync(0xffffffffu, sum1, off);
    }
    l0 = l0*al0 + sum0;
    l1 = l1*al1 + sum1;

    #pragma unroll
    for (int nt = 0; nt < 4; nt++) {
      oacc[nt][0] *= al0; oacc[nt][1] *= al0;
      oacc[nt][2] *= al1; oacc[nt][3] *= al1;
    }
    __syncwarp();

    #pragma unroll
    for (int kt = 0; kt < 8; kt++) {
      float ap[4];
      ap[0] = Ps[warp][gid    ][kt*8 + tig    ];
      ap[1] = Ps[warp][gid + 8][kt*8 + tig    ];
      ap[2] = Ps[warp][gid    ][kt*8 + tig + 4];
      ap[3] = Ps[warp][gid + 8][kt*8 + tig + 4];
      #pragma unroll
      for (int nt = 0; nt < 4; nt++) {
        float b[2];
        b[0] = Vt[nt*8 + gid][kt*8 + tig    ];
        b[1] = Vt[nt*8 + gid][kt*8 + tig + 4];
        mma_tf32(oacc[nt], ap, b);
      }
    }
  }

  float inv0 = 1.f / l0, inv1 = 1.f / l1;
  int rg0 = bn*DSEQ + q0 + warp*16 + gid;
  #pragma unroll
  for (int nt = 0; nt < 4; nt++) {
    int c0 = h*HSZ + nt*8 + tig*2;
    *(float2*)(O + (size_t)rg0*HDIM + c0)     = make_float2(oacc[nt][0]*inv0, oacc[nt][1]*inv0);
    *(float2*)(O + (size_t)(rg0+8)*HDIM + c0) = make_float2(oacc[nt][2]*inv1, oacc[nt][3]*inv1);
  }
}

// ------------------------- residual + LayerNorm --------------------------------
__global__ void add_ln_kernel(const float* __restrict__ Xin, const float* __restrict__ Y,
                              const float* __restrict__ g, const float* __restrict__ b,
                              float* __restrict__ Out) {
  __shared__ float red[256];
  int row = blockIdx.x, tid = threadIdx.x;
  float v = Xin[(size_t)row*HDIM + tid] + Y[(size_t)row*HDIM + tid];
  red[tid] = v; __syncthreads();
  for (int s = 128; s > 0; s >>= 1) { if (tid < s) red[tid] += red[tid+s]; __syncthreads(); }
  float mean = red[0] * (1.f/HDIM);
  __syncthreads();
  float dv = v - mean;
  red[tid] = dv*dv; __syncthreads();
  for (int s = 128; s > 0; s >>= 1) { if (tid < s) red[tid] += red[tid+s]; __syncthreads(); }
  float var = red[0] * (1.f/HDIM);
  Out[(size_t)row*HDIM + tid] = dv * rsqrtf(var + 1e-5f) * g[tid] + b[tid];
}

// ------------------------- cosine head ------------------------------------------
__global__ void rownorm_kernel(const float* __restrict__ In, float* __restrict__ Out) {
  __shared__ float red[256];
  int row = blockIdx.x, tid = threadIdx.x;
  float v = In[(size_t)row*HDIM + tid];
  red[tid] = v*v; __syncthreads();
  for (int s=128; s>0; s>>=1){ if(tid<s) red[tid]+=red[tid+s]; __syncthreads(); }
  float n = fmaxf(sqrtf(red[0]), 1e-8f);
  Out[(size_t)row*HDIM + tid] = v / n;
}

__global__ void dc_norm_kernel(const int* __restrict__ dtok, const float* __restrict__ embw,
                               const float* __restrict__ Xf, const float* __restrict__ wc,
                               const float* __restrict__ bc, float* __restrict__ DN) {
  __shared__ float red[256];
  int row = blockIdx.x, tid = threadIdx.x;
  float de = embw[(size_t)dtok[row]*HDIM + tid];
  float v = wc[0]*de + wc[1]*Xf[(size_t)row*HDIM + tid] + bc[0];
  red[tid] = v*v; __syncthreads();
  for (int s=128;s>0;s>>=1){ if(tid<s) red[tid]+=red[tid+s]; __syncthreads(); }
  float n = fmaxf(sqrtf(red[0]), 1e-8f);
  DN[(size_t)row*HDIM + tid] = v / n;
}

__global__ void cos_kernel(const float* __restrict__ QN, const float* __restrict__ DN,
                           float* __restrict__ COS) {
  __shared__ float Qs[NQ*HDIM];
  int bn = blockIdx.y;
  int b = bn >> 1;
  int t = blockIdx.x*128 + threadIdx.x;
  for (int i = threadIdx.x; i < NQ*HDIM; i += 128) Qs[i] = QN[(size_t)b*NQ*HDIM + i];
  __syncthreads();
  const float* dp = DN + ((size_t)bn*DSEQ + t)*HDIM;
  float acc[NQ] = {};
  for (int hh = 0; hh < HDIM; hh++) {
    float dv = dp[hh];
    #pragma unroll
    for (int qq = 0; qq < NQ; qq++) acc[qq] = fmaf(dv, Qs[qq*HDIM+hh], acc[qq]);
  }
  #pragma unroll
  for (int qq = 0; qq < NQ; qq++)
    COS[((size_t)bn*NQ + qq)*DSEQ + t] = acc[qq];
}

// ------------------------- RBF pooling ------------------------------------------
__global__ void rbf_y_kernel(const float* __restrict__ COS, const float* __restrict__ mask_d,
                             float* __restrict__ Y) {
  size_t idx = (size_t)blockIdx.x*256 + threadIdx.x;
  int k = (int)(idx & (KRBF-1));
  int row = (int)(idx >> 7);
  int dp = row % DPOOL;
  int bq = row / DPOOL;
  int bn = bq >> 4;
  const float* cr = COS + (size_t)bq*DSEQ + dp*2;
  const float* mr = mask_d + bn*DSEQ + dp*2;
  float mu = 1.f - (float)k*(2.f/KRBF);
  float s = 0.f;
  #pragma unroll
  for (int j = 0; j < 4; j++) {
    float c = cr[j] - mu;
    s += mr[j]*__expf(-50.f*c*c);
  }
  Y[idx] = __logf(s + 1e-6f);
}

__global__ void final_max_kernel(const float* __restrict__ SVp, const float* __restrict__ b2,
                                 float* __restrict__ SC) {
  __shared__ float red[256];
  int bq = blockIdx.x, tid = threadIdx.x;
  float mx = -1e30f;
  if (tid < DPOOL) {
    size_t r = (size_t)bq*DPOOL + tid;
    mx = SVp[r] + SVp[NRBFROWS + r];
  }
  red[tid] = mx; __syncthreads();
  for (int s=128;s>0;s>>=1){ if(tid<s) red[tid]=fmaxf(red[tid],red[tid+s]); __syncthreads(); }
  if (tid==0) SC[bq] = red[0] + b2[0];
}

__global__ void final_sum_kernel(const float* __restrict__ SC, const float* __restrict__ mask_q,
                                 float* __restrict__ out) {
  int bn = threadIdx.x;       // 32
  int b = bn >> 1;
  float s = 0.f;
  #pragma unroll
  for (int qq = 0; qq < NQ; qq++)
    s += SC[bn*NQ + qq] * mask_q[b*NQ + qq];
  out[bn] = s;
}

// ------------------------- launcher ---------------------------------------------
extern "C" void kernel_launch(void* const* d_in, const int* in_sizes, int n_in,
                              void* d_out, int out_size) {
  const int*   qtok     = (const int*)d_in[0];
  const int*   dtok     = (const int*)d_in[1];
  const float* mask_q   = (const float*)d_in[2];
  const float* mask_d   = (const float*)d_in[3];
  const float* embw     = (const float*)d_in[4];
  const float* fc_qt_w  = (const float*)d_in[5];
  const float* fc_qt_b  = (const float*)d_in[6];
  const float* qkv_w    = (const float*)d_in[7];
  const float* qkv_b    = (const float*)d_in[8];
  const float* out_w    = (const float*)d_in[9];
  const float* out_b    = (const float*)d_in[10];
  const float* ln1_g    = (const float*)d_in[11];
  const float* ln1_b    = (const float*)d_in[12];
  const float* w1       = (const float*)d_in[13];
  const float* b1       = (const float*)d_in[14];
  const float* w2       = (const float*)d_in[15];
  const float* b2       = (const float*)d_in[16];
  const float* ln2_g    = (const float*)d_in[17];
  const float* ln2_b    = (const float*)d_in[18];
  const float* fc_ctx_w = (const float*)d_in[19];
  const float* fc_ctx_b = (const float*)d_in[20];
  const float* rb1w     = (const float*)d_in[21];
  const float* rb1b     = (const float*)d_in[22];
  const float* rb2w     = (const float*)d_in[23];
  const float* rb2b     = (const float*)d_in[24];
  float* out = (float*)d_out;

  void* p;
  cudaGetSymbolAddress(&p, g_X);   float* X   = (float*)p;
  cudaGetSymbolAddress(&p, g_T);   float* T   = (float*)p;
  cudaGetSymbolAddress(&p, g_FF);  float* FF  = (float*)p;
  cudaGetSymbolAddress(&p, g_QKV); float* QKV = (float*)p;
  cudaGetSymbolAddress(&p, g_O);   float* O   = (float*)p;
  cudaGetSymbolAddress(&p, g_QE);  float* QE  = (float*)p;
  cudaGetSymbolAddress(&p, g_QT);  float* QT  = (float*)p;
  cudaGetSymbolAddress(&p, g_QN);  float* QN  = (float*)p;
  cudaGetSymbolAddress(&p, g_DN);  float* DN  = (float*)p;
  cudaGetSymbolAddress(&p, g_COS); float* COS = (float*)p;
  cudaGetSymbolAddress(&p, g_YR);  float* YR  = (float*)p;
  cudaGetSymbolAddress(&p, g_SVP); float* SVp = (float*)p;
  cudaGetSymbolAddress(&p, g_SC);  float* SC  = (float*)p;

  embed_doc_kernel<<<NROWS*HDIM/256, 256>>>(dtok, embw, X);

  for (int l = 0; l < NLAYER; l++) {
    gemm_tf32_kernel<false><<<dim3(768/128, NROWS/128), 256>>>(
        X, qkv_w + (size_t)l*HDIM*768, qkv_b + l*768, QKV, NROWS, 768, HDIM);
    attn_fused_kernel<<<dim3(DSEQ/64, NSEQ*NHEAD), 128>>>(QKV, mask_d, O);
    gemm_tf32_kernel<false><<<dim3(2, NROWS/128), 256>>>(
        O, out_w + (size_t)l*HDIM*HDIM, out_b + l*HDIM, T, NROWS, HDIM, HDIM);
    add_ln_kernel<<<NROWS,256>>>(X, T, ln1_g+l*HDIM, ln1_b+l*HDIM, X);
    gemm_tf32_kernel<true><<<dim3(2, NROWS/128), 256>>>(
        X, w1 + (size_t)l*HDIM*HDIM, b1 + l*HDIM, FF, NROWS, HDIM, HDIM);
    gemm_tf32_kernel<false><<<dim3(2, NROWS/128), 256>>>(
        FF, w2 + (size_t)l*HDIM*HDIM, b2 + l*HDIM, T, NROWS, HDIM, HDIM);
    add_ln_kernel<<<NROWS,256>>>(X, T, ln2_g+l*HDIM, ln2_b+l*HDIM, X);
  }

  embed_q_kernel<<<NQROWS*HDIM/256,256>>>(qtok, embw, QE);
  gemm_tf32_kernel<false><<<dim3(2, NQROWS/128), 256>>>(QE, fc_qt_w, fc_qt_b, QT, NQROWS, HDIM, HDIM);
  rownorm_kernel<<<NQROWS,256>>>(QT, QN);
  dc_norm_kernel<<<NROWS,256>>>(dtok, embw, X, fc_ctx_w, fc_ctx_b, DN);
  cos_kernel<<<dim3(DSEQ/128, NSEQ),128>>>(QN, DN, COS);

  rbf_y_kernel<<<NRBFROWS*KRBF/256, 256>>>(COS, mask_d, YR);
  gemm_rbf_fused_kernel<<<dim3(2, NRBFROWS/128), 256>>>(YR, rb1w, rb1b, rb2w, SVp);
  final_max_kernel<<<NBQ,256>>>(SVp, rb2b, SC);
  final_sum_kernel<<<1,32>>>(SC, mask_q, out);
}